// round 2
// baseline (speedup 1.0000x reference)
#include <cuda_runtime.h>
#include <cuda_bf16.h>
#include <math.h>
#include <stdint.h>

#define C 256
#define EPS 0.001f
#define SUMBLK 256
#define NCHUNKS 128
#define KS 16

// ---------------- scratch (no allocation allowed) ----------------
__device__ float g_psum[SUMBLK * C];                       // per-block channel sums
__device__ float g_pG2[(size_t)3 * NCHUNKS * 128 * 128];   // split-K SYRK partials (3 tile-pairs)
__device__ float g_G[C * C];                               // X^T X
__device__ float g_W[C * C];                               // L^{-1} (lower, upper zeroed)
__device__ float g_bias[C];                                // W @ m
__device__ __nv_bfloat16 g_Whi[C * C];                     // W hi plane (row-major [n][k])
__device__ __nv_bfloat16 g_Wlo[C * C];                     // W lo plane

__constant__ int c2_pi[3] = {0, 0, 1};
__constant__ int c2_pj[3] = {0, 1, 1};

// ---------------- mma helper ----------------
__device__ __forceinline__ void mma_bf16(float* d, const uint32_t* a, const uint32_t* b) {
    asm volatile(
        "mma.sync.aligned.m16n8k16.row.col.f32.bf16.bf16.f32 "
        "{%0,%1,%2,%3}, {%4,%5,%6,%7}, {%8,%9}, {%0,%1,%2,%3};\n"
        : "+f"(d[0]), "+f"(d[1]), "+f"(d[2]), "+f"(d[3])
        : "r"(a[0]), "r"(a[1]), "r"(a[2]), "r"(a[3]), "r"(b[0]), "r"(b[1]));
}

__device__ __forceinline__ uint32_t pack_bf16(__nv_bfloat16 lo, __nv_bfloat16 hi) {
    return (uint32_t)__bfloat16_as_ushort(lo) | ((uint32_t)__bfloat16_as_ushort(hi) << 16);
}

// ---------------- 1) per-channel partial sums ----------------
__global__ __launch_bounds__(256) void colsum_kernel(const float* __restrict__ x, int rows) {
    int c = threadIdx.x;
    int rows_per = rows / gridDim.x;
    const float* p = x + (size_t)blockIdx.x * rows_per * C + c;
    float s = 0.f;
#pragma unroll 8
    for (int r = 0; r < rows_per; ++r) s += p[(size_t)r * C];
    g_psum[blockIdx.x * C + c] = s;
}

// ---------------- 2) SYRK via bf16 hi/lo split tensor MMA ----------------
// grid (3 pairs, NCHUNKS). Block 256 thr = 8 warps (2x4), tile 128x128.
__global__ __launch_bounds__(256) void syrk_mma_kernel(const float* __restrict__ x, int rows) {
    __shared__ __nv_bfloat16 ph[256][18];   // [channel][k], padded
    __shared__ __nv_bfloat16 pl[256][18];
    const uint32_t* ph32 = (const uint32_t*)&ph[0][0];
    const uint32_t* pl32 = (const uint32_t*)&pl[0][0];

    int p = blockIdx.x;
    int ci = c2_pi[p] * 128, cj = c2_pj[p] * 128;
    int kper = rows / NCHUNKS;
    int k0 = blockIdx.y * kper;
    int tid = threadIdx.x, lane = tid & 31, warp = tid >> 5;
    int wm = warp >> 2, wn = warp & 3;      // 2 x 4 warps; warp tile 64m x 32n
    int g4 = lane >> 2, t4 = lane & 3;

    float acc[4][4][4];
#pragma unroll
    for (int i = 0; i < 4; ++i)
#pragma unroll
        for (int j = 0; j < 4; ++j)
#pragma unroll
            for (int r = 0; r < 4; ++r) acc[i][j][r] = 0.f;

    const float* xb = x + (size_t)k0 * C;

    for (int kk = 0; kk < kper; kk += KS) {
        // prefetch 16 rows x 256 channels (4 float4 per thread)
        float4 v[4];
#pragma unroll
        for (int q = 0; q < 4; ++q) {
            int f = tid * 4 + q;
            int r = f >> 6, c4 = f & 63;
            v[q] = *(const float4*)(xb + (size_t)(kk + r) * C + c4 * 4);
        }
        __syncthreads();
#pragma unroll
        for (int q = 0; q < 4; ++q) {
            int f = tid * 4 + q;
            int r = f >> 6, cc = (f & 63) * 4;
            float vv[4] = {v[q].x, v[q].y, v[q].z, v[q].w};
#pragma unroll
            for (int e = 0; e < 4; ++e) {
                __nv_bfloat16 h = __float2bfloat16_rn(vv[e]);
                __nv_bfloat16 l = __float2bfloat16_rn(vv[e] - __bfloat162float(h));
                ph[cc + e][r] = h;
                pl[cc + e][r] = l;
            }
        }
        __syncthreads();

        // B fragments (channel tile j), persistent across mf
        uint32_t bh[4][2], bl[4][2];
#pragma unroll
        for (int nf = 0; nf < 4; ++nf) {
            int n = cj + wn * 32 + nf * 8 + g4;
            bh[nf][0] = ph32[n * 9 + t4];     bh[nf][1] = ph32[n * 9 + t4 + 4];
            bl[nf][0] = pl32[n * 9 + t4];     bl[nf][1] = pl32[n * 9 + t4 + 4];
        }
#pragma unroll
        for (int mf = 0; mf < 4; ++mf) {
            int m = ci + wm * 64 + mf * 16 + g4;
            uint32_t ah[4], al[4];
            ah[0] = ph32[m * 9 + t4];         ah[1] = ph32[(m + 8) * 9 + t4];
            ah[2] = ph32[m * 9 + t4 + 4];     ah[3] = ph32[(m + 8) * 9 + t4 + 4];
            al[0] = pl32[m * 9 + t4];         al[1] = pl32[(m + 8) * 9 + t4];
            al[2] = pl32[m * 9 + t4 + 4];     al[3] = pl32[(m + 8) * 9 + t4 + 4];
#pragma unroll
            for (int nf = 0; nf < 4; ++nf) {
                mma_bf16(acc[mf][nf], ah, bh[nf]);   // Hi*Hi
                mma_bf16(acc[mf][nf], ah, bl[nf]);   // Hi*Lo
                mma_bf16(acc[mf][nf], al, bh[nf]);   // Lo*Hi
            }
        }
    }

    float* dst = g_pG2 + ((size_t)p * NCHUNKS + blockIdx.y) * 16384;
#pragma unroll
    for (int mf = 0; mf < 4; ++mf)
#pragma unroll
        for (int nf = 0; nf < 4; ++nf) {
            int r = wm * 64 + mf * 16 + g4;
            int c = wn * 32 + nf * 8 + t4 * 2;
            dst[r * 128 + c]           = acc[mf][nf][0];
            dst[r * 128 + c + 1]       = acc[mf][nf][1];
            dst[(r + 8) * 128 + c]     = acc[mf][nf][2];
            dst[(r + 8) * 128 + c + 1] = acc[mf][nf][3];
        }
}

// ---------------- 3) deterministic reduction of SYRK partials ----------------
__global__ __launch_bounds__(256) void reduceG2_kernel() {
    int p = blockIdx.x;
    int e = blockIdx.y * 256 + threadIdx.x;   // 0..16383
    const float* src = g_pG2 + (size_t)p * NCHUNKS * 16384 + e;
    float s = 0.f;
#pragma unroll 8
    for (int c = 0; c < NCHUNKS; ++c) s += src[(size_t)c * 16384];
    int a = e >> 7, b = e & 127;
    int gi = c2_pi[p] * 128 + a, gj = c2_pj[p] * 128 + b;
    g_G[gi * C + gj] = s;
    g_G[gj * C + gi] = s;
}

// ---------------- 4) mean + Cholesky + L^{-1} + bias + W bf16 split ----------------
extern "C" __global__ __launch_bounds__(256) void chol_kernel(int rows) {
    extern __shared__ float Lp[];
    __shared__ float m[C];
    int tid = threadIdx.x;

    // mean (fixed-order)
    {
        float s = 0.f;
#pragma unroll 8
        for (int b = 0; b < SUMBLK; ++b) s += g_psum[b * C + tid];
        m[tid] = s / (float)rows;
    }
    __syncthreads();

    // build packed A = (1-eps)/(n-1) * (G - n m m^T) + eps I
    const int TOT = C * (C + 1) / 2;
    float scale = (1.f - EPS) / (float)(rows - 1);
    for (int idx = tid; idx < TOT; idx += 256) {
        int i = (int)((sqrtf(8.f * (float)idx + 1.f) - 1.f) * 0.5f);
        while ((i + 1) * (i + 2) / 2 <= idx) ++i;
        while (i * (i + 1) / 2 > idx) --i;
        int j = idx - i * (i + 1) / 2;
        float v = (g_G[i * C + j] - (float)rows * m[i] * m[j]) * scale;
        if (i == j) v += EPS;
        Lp[idx] = v;
    }
    __syncthreads();

    // in-place packed Cholesky
    for (int k = 0; k < C; ++k) {
        int pk = k * (k + 1) / 2 + k;
        if (tid == 0) Lp[pk] = sqrtf(Lp[pk]);
        __syncthreads();
        float inv = 1.f / Lp[pk];
        int i = k + 1 + tid;
        if (i < C) Lp[i * (i + 1) / 2 + k] *= inv;
        __syncthreads();
        if (i < C) {
            float* row = &Lp[i * (i + 1) / 2];
            float lik = row[k];
#pragma unroll 4
            for (int j = k + 1; j <= i; ++j)
                row[j] -= lik * Lp[j * (j + 1) / 2 + k];
        }
        __syncthreads();
    }

    // W = L^{-1}: thread tid owns column tid
    {
        int j = tid;
        float wloc[C];
        for (int i = j; i < C; ++i) {
            const float* lrow = &Lp[i * (i + 1) / 2];
            float s = (i == j) ? 1.f : 0.f;
#pragma unroll 4
            for (int k = j; k < i; ++k) s -= lrow[k] * wloc[k];
            float w = s / lrow[i];
            wloc[i] = w;
            g_W[i * C + j] = w;
        }
        for (int i = 0; i < j; ++i) g_W[i * C + j] = 0.f;
    }
    __syncthreads();

    // bias = W @ m
    {
        float s = 0.f;
#pragma unroll 4
        for (int j = 0; j <= tid; ++j) s += g_W[tid * C + j] * m[j];
        g_bias[tid] = s;
    }

    // bf16 hi/lo split of W for the whitening MMA
    for (int idx = tid; idx < C * C; idx += 256) {
        float w = g_W[idx];
        __nv_bfloat16 h = __float2bfloat16_rn(w);
        g_Whi[idx] = h;
        g_Wlo[idx] = __float2bfloat16_rn(w - __bfloat162float(h));
    }
}

// ---------------- 5) whitening via bf16 hi/lo split tensor MMA ----------------
// Block: 512 thr = 16 warps (4x4), tile M=128 rows x N=256 out-channels, K=256.
__global__ __launch_bounds__(512) void whiten_mma_kernel(const float* __restrict__ x,
                                                         float* __restrict__ out) {
    __shared__ __nv_bfloat16 xh[128][18], xl[128][18];
    __shared__ __nv_bfloat16 wh[256][18], wl[256][18];
    __shared__ float sbias[C];
    const uint32_t* xh32 = (const uint32_t*)&xh[0][0];
    const uint32_t* xl32 = (const uint32_t*)&xl[0][0];
    const uint32_t* wh32 = (const uint32_t*)&wh[0][0];
    const uint32_t* wl32 = (const uint32_t*)&wl[0][0];

    int tid = threadIdx.x, lane = tid & 31, warp = tid >> 5;
    int wm = warp >> 2, wn = warp & 3;      // 4 x 4 warps; warp tile 32m x 64n
    int g4 = lane >> 2, t4 = lane & 3;
    size_t m0 = (size_t)blockIdx.x * 128;

    if (tid < C) sbias[tid] = g_bias[tid];

    float acc[2][8][4];
#pragma unroll
    for (int i = 0; i < 2; ++i)
#pragma unroll
        for (int j = 0; j < 8; ++j)
#pragma unroll
            for (int r = 0; r < 4; ++r) acc[i][j][r] = 0.f;

    const uint32_t* gwh = (const uint32_t*)g_Whi;
    const uint32_t* gwl = (const uint32_t*)g_Wlo;
    int xrow = tid >> 2, xq = tid & 3;

    for (int k0 = 0; k0 < C; k0 += KS) {
        // prefetch x slab (1 float4/thread) and W slabs (4+4 u32/thread)
        float4 xv = *(const float4*)(x + (m0 + xrow) * C + k0 + xq * 4);
        uint32_t whv[4], wlv[4];
#pragma unroll
        for (int q = 0; q < 4; ++q) {
            int idx = tid * 4 + q;              // 0..2047
            int n = idx >> 3, j = idx & 7;
            whv[q] = gwh[n * 128 + (k0 >> 1) + j];
            wlv[q] = gwl[n * 128 + (k0 >> 1) + j];
        }
        __syncthreads();
        {
            float vv[4] = {xv.x, xv.y, xv.z, xv.w};
            __nv_bfloat16 h[4], l[4];
#pragma unroll
            for (int e = 0; e < 4; ++e) {
                h[e] = __float2bfloat16_rn(vv[e]);
                l[e] = __float2bfloat16_rn(vv[e] - __bfloat162float(h[e]));
            }
            ((uint32_t*)&xh[0][0])[xrow * 9 + xq * 2]     = pack_bf16(h[0], h[1]);
            ((uint32_t*)&xh[0][0])[xrow * 9 + xq * 2 + 1] = pack_bf16(h[2], h[3]);
            ((uint32_t*)&xl[0][0])[xrow * 9 + xq * 2]     = pack_bf16(l[0], l[1]);
            ((uint32_t*)&xl[0][0])[xrow * 9 + xq * 2 + 1] = pack_bf16(l[2], l[3]);
        }
#pragma unroll
        for (int q = 0; q < 4; ++q) {
            int idx = tid * 4 + q;
            int n = idx >> 3, j = idx & 7;
            ((uint32_t*)&wh[0][0])[n * 9 + j] = whv[q];
            ((uint32_t*)&wl[0][0])[n * 9 + j] = wlv[q];
        }
        __syncthreads();

        // process n in two halves of 4 frags to cap register pressure
#pragma unroll
        for (int half = 0; half < 2; ++half) {
            uint32_t bh[4][2], bl[4][2];
#pragma unroll
            for (int nf = 0; nf < 4; ++nf) {
                int n = wn * 64 + (half * 4 + nf) * 8 + g4;
                bh[nf][0] = wh32[n * 9 + t4]; bh[nf][1] = wh32[n * 9 + t4 + 4];
                bl[nf][0] = wl32[n * 9 + t4]; bl[nf][1] = wl32[n * 9 + t4 + 4];
            }
#pragma unroll
            for (int mf = 0; mf < 2; ++mf) {
                int m = wm * 32 + mf * 16 + g4;
                uint32_t ah[4], al[4];
                ah[0] = xh32[m * 9 + t4];       ah[1] = xh32[(m + 8) * 9 + t4];
                ah[2] = xh32[m * 9 + t4 + 4];   ah[3] = xh32[(m + 8) * 9 + t4 + 4];
                al[0] = xl32[m * 9 + t4];       al[1] = xl32[(m + 8) * 9 + t4];
                al[2] = xl32[m * 9 + t4 + 4];   al[3] = xl32[(m + 8) * 9 + t4 + 4];
#pragma unroll
                for (int nf = 0; nf < 4; ++nf) {
                    mma_bf16(acc[mf][half * 4 + nf], ah, bh[nf]);
                    mma_bf16(acc[mf][half * 4 + nf], ah, bl[nf]);
                    mma_bf16(acc[mf][half * 4 + nf], al, bh[nf]);
                }
            }
        }
    }

    // epilogue: subtract bias, store
#pragma unroll
    for (int mf = 0; mf < 2; ++mf)
#pragma unroll
        for (int nf = 0; nf < 8; ++nf) {
            int r = wm * 32 + mf * 16 + g4;
            int c = wn * 64 + nf * 8 + t4 * 2;
            float b0 = sbias[c], b1 = sbias[c + 1];
            float2 v0 = make_float2(acc[mf][nf][0] - b0, acc[mf][nf][1] - b1);
            float2 v1 = make_float2(acc[mf][nf][2] - b0, acc[mf][nf][3] - b1);
            *(float2*)&out[(m0 + r) * C + c]     = v0;
            *(float2*)&out[(m0 + r + 8) * C + c] = v1;
        }
}

// ---------------- launch ----------------
extern "C" void kernel_launch(void* const* d_in, const int* in_sizes, int n_in,
                              void* d_out, int out_size) {
    const float* x = (const float*)d_in[0];
    float* out = (float*)d_out;
    int rows = in_sizes[0] / C;          // 131072 for (32,64,64,256)

    colsum_kernel<<<SUMBLK, 256>>>(x, rows);
    syrk_mma_kernel<<<dim3(3, NCHUNKS), 256>>>(x, rows);
    reduceG2_kernel<<<dim3(3, 64), 256>>>();

    static const int chol_smem = (C * (C + 1) / 2) * (int)sizeof(float);  // 131584
    cudaFuncSetAttribute(chol_kernel, cudaFuncAttributeMaxDynamicSharedMemorySize, chol_smem);
    chol_kernel<<<1, 256, chol_smem>>>(rows);

    whiten_mma_kernel<<<rows / 128, 512>>>(x, out);
}

// round 4
// speedup vs baseline: 1.4534x; 1.4534x over previous
#include <cuda_runtime.h>
#include <cuda_bf16.h>
#include <math.h>
#include <stdint.h>

#define C 256
#define ROWS 131072
#define EPS 0.001f
#define NSPLIT 2048
#define NBY 64               // syrk split-K blocks
#define SY_NCH 64            // chunks per syrk block (2048/32)
#define WH_NCH 8             // whiten k-chunks (256/32)

// ---------------- scratch ----------------
__device__ __nv_bfloat16 g_xhT[(size_t)C * ROWS];   // transposed hi plane [ch][row]
__device__ __nv_bfloat16 g_xlT[(size_t)C * ROWS];   // transposed lo plane
__device__ float g_psum[NSPLIT * C];
__device__ float g_psum2[16 * C];
__device__ float g_pG2[(size_t)3 * NBY * 128 * 128];
__device__ float g_G[C * C];
__device__ float g_W[C * C];
__device__ float g_bias[C];
__device__ __nv_bfloat16 g_Whi[C * C];
__device__ __nv_bfloat16 g_Wlo[C * C];

__constant__ int c2_pi[3] = {0, 0, 1};
__constant__ int c2_pj[3] = {0, 1, 1};

// ---------------- helpers ----------------
__device__ __forceinline__ uint32_t smem_u32(const void* p) {
    uint32_t a;
    asm("{ .reg .u64 t; cvta.to.shared.u64 t, %1; cvt.u32.u64 %0, t; }" : "=r"(a) : "l"(p));
    return a;
}
__device__ __forceinline__ void cp16(uint32_t dst, const void* src) {
    asm volatile("cp.async.cg.shared.global [%0], [%1], 16;" :: "r"(dst), "l"(src));
}
#define CP_COMMIT() asm volatile("cp.async.commit_group;" ::: "memory")
#define CP_WAIT1()  asm volatile("cp.async.wait_group 1;" ::: "memory")
#define CP_WAIT0()  asm volatile("cp.async.wait_group 0;" ::: "memory")

__device__ __forceinline__ void mma_bf16(float* d, const uint32_t* a, const uint32_t* b) {
    asm volatile(
        "mma.sync.aligned.m16n8k16.row.col.f32.bf16.bf16.f32 "
        "{%0,%1,%2,%3}, {%4,%5,%6,%7}, {%8,%9}, {%0,%1,%2,%3};\n"
        : "+f"(d[0]), "+f"(d[1]), "+f"(d[2]), "+f"(d[3])
        : "r"(a[0]), "r"(a[1]), "r"(a[2]), "r"(a[3]), "r"(b[0]), "r"(b[1]));
}
__device__ __forceinline__ uint32_t pack2(__nv_bfloat16 lo, __nv_bfloat16 hi) {
    return (uint32_t)__bfloat16_as_ushort(lo) | ((uint32_t)__bfloat16_as_ushort(hi) << 16);
}

// ---------------- 1) split x -> transposed bf16 hi/lo planes + channel sums ----------------
__global__ __launch_bounds__(256) void split_kernel(const float* __restrict__ x) {
    __shared__ float stage[64][261];
    __shared__ float csum[4][C];
    int tid = threadIdx.x;
    size_t r0 = (size_t)blockIdx.x * 64;
    int c4 = tid & 63, rr = tid >> 6;
    float s0 = 0, s1 = 0, s2 = 0, s3 = 0;
#pragma unroll 4
    for (int i = 0; i < 16; ++i) {
        int r = 4 * i + rr;
        float4 v = *(const float4*)(x + (r0 + r) * C + c4 * 4);
        stage[r][c4 * 4 + 0] = v.x; stage[r][c4 * 4 + 1] = v.y;
        stage[r][c4 * 4 + 2] = v.z; stage[r][c4 * 4 + 3] = v.w;
        s0 += v.x; s1 += v.y; s2 += v.z; s3 += v.w;
    }
    csum[rr][c4 * 4 + 0] = s0; csum[rr][c4 * 4 + 1] = s1;
    csum[rr][c4 * 4 + 2] = s2; csum[rr][c4 * 4 + 3] = s3;
    __syncthreads();
    if (tid < C)
        g_psum[blockIdx.x * C + tid] = csum[0][tid] + csum[1][tid] + csum[2][tid] + csum[3][tid];

    int r2 = tid & 31, chb = tid >> 5;
    uint32_t* dH = (uint32_t*)g_xhT;
    uint32_t* dL = (uint32_t*)g_xlT;
    size_t rbase = r0 >> 1;
#pragma unroll 4
    for (int k = 0; k < 32; ++k) {
        int ch = chb + 8 * k;
        float f0 = stage[2 * r2][ch], f1 = stage[2 * r2 + 1][ch];
        __nv_bfloat16 h0 = __float2bfloat16_rn(f0), h1 = __float2bfloat16_rn(f1);
        __nv_bfloat16 l0 = __float2bfloat16_rn(f0 - __bfloat162float(h0));
        __nv_bfloat16 l1 = __float2bfloat16_rn(f1 - __bfloat162float(h1));
        dH[(size_t)ch * (ROWS / 2) + rbase + r2] = pack2(h0, h1);
        dL[(size_t)ch * (ROWS / 2) + rbase + r2] = pack2(l0, l1);
    }
}

__global__ __launch_bounds__(256) void psum_reduce() {
    float s = 0.f;
    int b0 = blockIdx.x * 128;
#pragma unroll 8
    for (int i = 0; i < 128; ++i) s += g_psum[(b0 + i) * C + threadIdx.x];
    g_psum2[blockIdx.x * C + threadIdx.x] = s;
}

// ---------------- 2) SYRK: 128x128 tile pairs, cp.async double buffer, mma.sync ----------------
// smem: stage s (2), tile t (AH,AL,BH,BL), each 8KB: [slab 2][ch 128][32B]
__global__ __launch_bounds__(256) void syrk_mma(int dummy) {
    extern __shared__ char smem[];
    uint32_t sb = smem_u32(smem);
    const uint32_t* s32 = (const uint32_t*)smem;

    int tid = threadIdx.x, lane = tid & 31, warp = tid >> 5;
    int wm = warp >> 2, wn = warp & 3;          // 2x4 warps, warp tile 64x32
    int g4 = lane >> 2, t4 = lane & 3;
    int p = blockIdx.x;
    int ti = c2_pi[p], tj = c2_pj[p];
    size_t k0base = (size_t)blockIdx.y * (ROWS / NBY);

    float acc[4][4][4];
#pragma unroll
    for (int a = 0; a < 4; ++a)
#pragma unroll
        for (int b = 0; b < 4; ++b)
#pragma unroll
            for (int r = 0; r < 4; ++r) acc[a][b][r] = 0.f;

    // issue loads for chunk cc into stage s
    auto issue = [&](int cc, int s) {
        size_t k0 = k0base + (size_t)cc * 32;
#pragma unroll
        for (int q = 0; q < 8; ++q) {
            int idx = tid + 256 * q;            // 0..2047
            int t = idx >> 9;                   // 0..3 : AH AL BH BL
            int ch = (idx >> 2) & 127;
            int pc = idx & 3;                   // 16B piece (8 bf16 = 8 k)
            const __nv_bfloat16* plane = (t & 1) ? g_xlT : g_xhT;
            int cb = ((t < 2) ? ti : tj) * 128;
            const void* src = plane + (size_t)(cb + ch) * ROWS + k0 + pc * 8;
            uint32_t dst = sb + (uint32_t)s * 32768 + (uint32_t)t * 8192 +
                           (uint32_t)(pc >> 1) * 4096 + (uint32_t)ch * 32 + (uint32_t)(pc & 1) * 16;
            cp16(dst, src);
        }
    };

    issue(0, 0); CP_COMMIT();
    for (int c = 0; c < SY_NCH; ++c) {
        int s = c & 1;
        __syncthreads();
        if (c + 1 < SY_NCH) { issue(c + 1, s ^ 1); CP_COMMIT(); CP_WAIT1(); }
        else CP_WAIT0();
        __syncthreads();

        uint32_t AH = (uint32_t)s * 8192 + 0;         // u32 index base into s32
        uint32_t AL = AH + 2048, BH = AH + 4096, BL = AH + 6144;
#pragma unroll
        for (int ks = 0; ks < 2; ++ks) {
            uint32_t so = (uint32_t)ks * 1024;
            uint32_t bh[4][2], bl[4][2];
#pragma unroll
            for (int nf = 0; nf < 4; ++nf) {
                int n = wn * 32 + nf * 8 + g4;
                bh[nf][0] = s32[BH + so + n * 8 + t4];   bh[nf][1] = s32[BH + so + n * 8 + t4 + 4];
                bl[nf][0] = s32[BL + so + n * 8 + t4];   bl[nf][1] = s32[BL + so + n * 8 + t4 + 4];
            }
#pragma unroll
            for (int mf = 0; mf < 4; ++mf) {
                int m = wm * 64 + mf * 16 + g4;
                uint32_t ah[4], al[4];
                ah[0] = s32[AH + so + m * 8 + t4];       ah[1] = s32[AH + so + (m + 8) * 8 + t4];
                ah[2] = s32[AH + so + m * 8 + t4 + 4];   ah[3] = s32[AH + so + (m + 8) * 8 + t4 + 4];
                al[0] = s32[AL + so + m * 8 + t4];       al[1] = s32[AL + so + (m + 8) * 8 + t4];
                al[2] = s32[AL + so + m * 8 + t4 + 4];   al[3] = s32[AL + so + (m + 8) * 8 + t4 + 4];
#pragma unroll
                for (int nf = 0; nf < 4; ++nf) {
                    mma_bf16(acc[mf][nf], ah, bh[nf]);
                    mma_bf16(acc[mf][nf], ah, bl[nf]);
                    mma_bf16(acc[mf][nf], al, bh[nf]);
                }
            }
        }
    }

    float* dst = g_pG2 + ((size_t)p * NBY + blockIdx.y) * 16384;
#pragma unroll
    for (int mf = 0; mf < 4; ++mf)
#pragma unroll
        for (int nf = 0; nf < 4; ++nf) {
            int r = wm * 64 + mf * 16 + g4;
            int cc = wn * 32 + nf * 8 + t4 * 2;
            dst[r * 128 + cc]           = acc[mf][nf][0];
            dst[r * 128 + cc + 1]       = acc[mf][nf][1];
            dst[(r + 8) * 128 + cc]     = acc[mf][nf][2];
            dst[(r + 8) * 128 + cc + 1] = acc[mf][nf][3];
        }
}

// ---------------- 3) deterministic reduction ----------------
__global__ __launch_bounds__(256) void reduceG2_kernel() {
    int p = blockIdx.x;
    int e = blockIdx.y * 256 + threadIdx.x;   // 0..16383
    const float* src = g_pG2 + (size_t)p * NBY * 16384 + e;
    float s = 0.f;
#pragma unroll 8
    for (int c = 0; c < NBY; ++c) s += src[(size_t)c * 16384];
    int a = e >> 7, b = e & 127;
    int gi = c2_pi[p] * 128 + a, gj = c2_pj[p] * 128 + b;
    g_G[gi * C + gj] = s;
    g_G[gj * C + gi] = s;
}

// ---------------- 4) mean + Cholesky + blocked L^{-1} + bias + W split ----------------
extern "C" __global__ __launch_bounds__(256) void chol_kernel(int rows) {
    extern __shared__ float Lp[];     // packed lower tri, 32896 floats
    __shared__ float m[C];
    __shared__ float scr[32 * 32];
    int tid = threadIdx.x;

    {
        float s = 0.f;
#pragma unroll
        for (int b = 0; b < 16; ++b) s += g_psum2[b * C + tid];
        m[tid] = s / (float)rows;
    }
    __syncthreads();

    const int TOT = C * (C + 1) / 2;
    float scale = (1.f - EPS) / (float)(rows - 1);
    for (int idx = tid; idx < TOT; idx += 256) {
        int i = (int)((sqrtf(8.f * (float)idx + 1.f) - 1.f) * 0.5f);
        while ((i + 1) * (i + 2) / 2 <= idx) ++i;
        while (i * (i + 1) / 2 > idx) --i;
        int j = idx - i * (i + 1) / 2;
        float v = (g_G[i * C + j] - (float)rows * m[i] * m[j]) * scale;
        if (i == j) v += EPS;
        Lp[idx] = v;
    }
    __syncthreads();

    // in-place packed Cholesky
    for (int k = 0; k < C; ++k) {
        int pk = k * (k + 1) / 2 + k;
        if (tid == 0) Lp[pk] = sqrtf(Lp[pk]);
        __syncthreads();
        float inv = 1.f / Lp[pk];
        int i = k + 1 + tid;
        if (i < C) Lp[i * (i + 1) / 2 + k] *= inv;
        __syncthreads();
        if (i < C) {
            float* row = &Lp[i * (i + 1) / 2];
            float lik = row[k];
#pragma unroll 4
            for (int j = k + 1; j <= i; ++j)
                row[j] -= lik * Lp[j * (j + 1) / 2 + k];
        }
        __syncthreads();
    }

    // ---- blocked inversion: diagonal 32x32 blocks, fully in registers ----
    {
        int b = tid >> 5, j = tid & 31;
        int rb = b * 32;
        float w[32];
#pragma unroll
        for (int i = 0; i < 32; ++i) {
            float s = (i == j) ? 1.f : 0.f;
            const float* lrow = &Lp[(rb + i) * (rb + i + 1) / 2 + rb];
#pragma unroll
            for (int k = 0; k < 32; ++k)
                if (k < i) s -= lrow[k] * w[k];
            w[i] = (i >= j) ? s / lrow[i] : 0.f;
        }
#pragma unroll
        for (int i = 0; i < 32; ++i) g_W[(rb + i) * C + rb + j] = w[i];
    }
    __syncthreads();
    // zero everything outside the 8 diagonal blocks' lower part that is upper-triangular
    for (int idx = tid; idx < C * C; idx += 256) {
        int r = idx >> 8, cc = idx & 255;
        if (cc > r) g_W[idx] = 0.f;
    }
    __syncthreads();

    // ---- off-diagonal blocks: W(bi,bj) = -Dinv_bi * sum_{kb=bj..bi-1} L(bi,kb) W(kb,bj) ----
    {
        int r = tid >> 3, c4 = (tid & 7) * 4;
        for (int step = 1; step < 8; ++step) {
            for (int bj = 0; bj + step < 8; ++bj) {
                int bi = bj + step;
                float a0 = 0, a1 = 0, a2 = 0, a3 = 0;
                const float* lrow = &Lp[(bi * 32 + r) * (bi * 32 + r + 1) / 2];
                for (int kb = bj; kb < bi; ++kb) {
#pragma unroll 8
                    for (int kk = 0; kk < 32; ++kk) {
                        float lv = lrow[kb * 32 + kk];
                        const float* wr = &g_W[(kb * 32 + kk) * C + bj * 32 + c4];
                        a0 += lv * wr[0]; a1 += lv * wr[1]; a2 += lv * wr[2]; a3 += lv * wr[3];
                    }
                }
                scr[r * 32 + c4 + 0] = a0; scr[r * 32 + c4 + 1] = a1;
                scr[r * 32 + c4 + 2] = a2; scr[r * 32 + c4 + 3] = a3;
                __syncthreads();
                float o0 = 0, o1 = 0, o2 = 0, o3 = 0;
#pragma unroll 8
                for (int kk = 0; kk < 32; ++kk) {
                    float dv = g_W[(bi * 32 + r) * C + bi * 32 + kk];
                    o0 += dv * scr[kk * 32 + c4 + 0];
                    o1 += dv * scr[kk * 32 + c4 + 1];
                    o2 += dv * scr[kk * 32 + c4 + 2];
                    o3 += dv * scr[kk * 32 + c4 + 3];
                }
                g_W[(bi * 32 + r) * C + bj * 32 + c4 + 0] = -o0;
                g_W[(bi * 32 + r) * C + bj * 32 + c4 + 1] = -o1;
                g_W[(bi * 32 + r) * C + bj * 32 + c4 + 2] = -o2;
                g_W[(bi * 32 + r) * C + bj * 32 + c4 + 3] = -o3;
                __syncthreads();
            }
        }
    }

    // bias = W @ m
    {
        float s = 0.f;
#pragma unroll 4
        for (int j = 0; j <= tid; ++j) s += g_W[tid * C + j] * m[j];
        g_bias[tid] = s;
    }

    // bf16 hi/lo split of W
    for (int idx = tid; idx < C * C; idx += 256) {
        float w = g_W[idx];
        __nv_bfloat16 h = __float2bfloat16_rn(w);
        g_Whi[idx] = h;
        g_Wlo[idx] = __float2bfloat16_rn(w - __bfloat162float(h));
    }
}

// ---------------- 5) whitening: out = x W^T - bias (cp.async pipeline + mma.sync) ----------------
// smem layout (bytes): xs fp32 stages [2][128][128B] = 32768
//                      xplanes [2][plane2][slab2][128][32B] at 32768 (+16384/stage)
//                      W planes [2][plane2][slab2][256][32B] at 65536 (+32768/stage)
__global__ __launch_bounds__(512) void whiten_mma(const float* __restrict__ x,
                                                  float* __restrict__ out) {
    extern __shared__ char smem[];
    __shared__ float sbias[C];
    uint32_t sb = smem_u32(smem);
    const uint32_t* s32 = (const uint32_t*)smem;
    const float* sf = (const float*)smem;

    int tid = threadIdx.x, lane = tid & 31, warp = tid >> 5;
    int wm = warp >> 2, wn = warp & 3;      // 4x4 warps, warp tile 32x64
    int g4 = lane >> 2, t4 = lane & 3;
    size_t m0 = (size_t)blockIdx.x * 128;

    if (tid < C) sbias[tid] = g_bias[tid];

    float acc[2][8][4];
#pragma unroll
    for (int a = 0; a < 2; ++a)
#pragma unroll
        for (int b = 0; b < 8; ++b)
#pragma unroll
            for (int r = 0; r < 4; ++r) acc[a][b][r] = 0.f;

    auto issue = [&](int cc, int s) {
        int k0 = cc * 32;
        // x fp32: 1024 x 16B
#pragma unroll
        for (int q = 0; q < 2; ++q) {
            int idx = tid * 2 + q;
            int row = idx >> 3, pc = idx & 7;
            cp16(sb + (uint32_t)s * 16384 + (uint32_t)row * 128 + (uint32_t)pc * 16,
                 x + (m0 + row) * C + k0 + pc * 4);
        }
        // W planes: 2048 x 16B
#pragma unroll
        for (int q = 0; q < 4; ++q) {
            int idx = tid + 512 * q;
            int pl = idx >> 10, n = (idx >> 2) & 255, pc = idx & 3;
            const __nv_bfloat16* plane = pl ? g_Wlo : g_Whi;
            cp16(sb + 65536u + (uint32_t)s * 32768 + (uint32_t)pl * 16384 +
                     (uint32_t)(pc >> 1) * 8192 + (uint32_t)n * 32 + (uint32_t)(pc & 1) * 16,
                 plane + (size_t)n * C + k0 + pc * 8);
        }
    };

    issue(0, 0); CP_COMMIT();
    for (int c = 0; c < WH_NCH; ++c) {
        int s = c & 1;
        __syncthreads();
        if (c + 1 < WH_NCH) { issue(c + 1, s ^ 1); CP_COMMIT(); CP_WAIT1(); }
        else CP_WAIT0();
        __syncthreads();

        // convert x fp32 stage -> bf16 hi/lo planes
        {
            int row = tid >> 2, oct = tid & 3;          // 8 k per thread
            uint32_t xbase = (uint32_t)s * 4096 + (uint32_t)row * 32 + (uint32_t)oct * 8; // f32 idx
            float4 fa = *(const float4*)(sf + xbase);
            float4 fb = *(const float4*)(sf + xbase + 4);
            float f[8] = {fa.x, fa.y, fa.z, fa.w, fb.x, fb.y, fb.z, fb.w};
            uint32_t hp[4], lp[4];
#pragma unroll
            for (int e = 0; e < 4; ++e) {
                __nv_bfloat16 h0 = __float2bfloat16_rn(f[2 * e]);
                __nv_bfloat16 h1 = __float2bfloat16_rn(f[2 * e + 1]);
                __nv_bfloat16 l0 = __float2bfloat16_rn(f[2 * e] - __bfloat162float(h0));
                __nv_bfloat16 l1 = __float2bfloat16_rn(f[2 * e + 1] - __bfloat162float(h1));
                hp[e] = pack2(h0, h1);
                lp[e] = pack2(l0, l1);
            }
            uint32_t db = 8192u + (uint32_t)s * 4096 +           // u32 index: 32768B + s*16384B
                          (uint32_t)(oct >> 1) * 1024 + (uint32_t)row * 8 + (uint32_t)(oct & 1) * 4;
            *(uint4*)((uint32_t*)smem + db) = make_uint4(hp[0], hp[1], hp[2], hp[3]);
            *(uint4*)((uint32_t*)smem + db + 2048) = make_uint4(lp[0], lp[1], lp[2], lp[3]); // lo plane +8192B
        }
        __syncthreads();

        uint32_t XH = 8192u + (uint32_t)s * 4096;        // u32 idx
        uint32_t XL = XH + 2048;
        uint32_t WH = 16384u + (uint32_t)s * 8192;       // 65536B base
        uint32_t WL = WH + 4096;
#pragma unroll
        for (int ks = 0; ks < 2; ++ks) {
            uint32_t xo = (uint32_t)ks * 1024, wo = (uint32_t)ks * 2048;
            uint32_t ah[4], al[4];
#pragma unroll
            for (int mf = 0; mf < 2; ++mf) {
                int mrow = wm * 32 + mf * 16 + g4;
                ah[0] = s32[XH + xo + mrow * 8 + t4];     ah[1] = s32[XH + xo + (mrow + 8) * 8 + t4];
                ah[2] = s32[XH + xo + mrow * 8 + t4 + 4]; ah[3] = s32[XH + xo + (mrow + 8) * 8 + t4 + 4];
                al[0] = s32[XL + xo + mrow * 8 + t4];     al[1] = s32[XL + xo + (mrow + 8) * 8 + t4];
                al[2] = s32[XL + xo + mrow * 8 + t4 + 4]; al[3] = s32[XL + xo + (mrow + 8) * 8 + t4 + 4];
#pragma unroll
                for (int nf = 0; nf < 8; ++nf) {
                    int n = wn * 64 + nf * 8 + g4;
                    uint32_t bh[2], bl[2];
                    bh[0] = s32[WH + wo + n * 8 + t4];    bh[1] = s32[WH + wo + n * 8 + t4 + 4];
                    bl[0] = s32[WL + wo + n * 8 + t4];    bl[1] = s32[WL + wo + n * 8 + t4 + 4];
                    mma_bf16(acc[mf][nf], ah, bh);
                    mma_bf16(acc[mf][nf], ah, bl);
                    mma_bf16(acc[mf][nf], al, bh);
                }
            }
        }
    }

    // epilogue
#pragma unroll
    for (int mf = 0; mf < 2; ++mf)
#pragma unroll
        for (int nf = 0; nf < 8; ++nf) {
            int r = wm * 32 + mf * 16 + g4;
            int cc = wn * 64 + nf * 8 + t4 * 2;
            float b0 = sbias[cc], b1 = sbias[cc + 1];
            *(float2*)&out[(m0 + r) * C + cc]     = make_float2(acc[mf][nf][0] - b0, acc[mf][nf][1] - b1);
            *(float2*)&out[(m0 + r + 8) * C + cc] = make_float2(acc[mf][nf][2] - b0, acc[mf][nf][3] - b1);
        }
}

// ---------------- launch ----------------
extern "C" void kernel_launch(void* const* d_in, const int* in_sizes, int n_in,
                              void* d_out, int out_size) {
    const float* x = (const float*)d_in[0];
    float* out = (float*)d_out;
    int rows = in_sizes[0] / C;          // 131072

    split_kernel<<<NSPLIT, 256>>>(x);
    psum_reduce<<<16, 256>>>();

    static const int syrk_smem = 65536;
    cudaFuncSetAttribute(syrk_mma, cudaFuncAttributeMaxDynamicSharedMemorySize, syrk_smem);
    syrk_mma<<<dim3(3, NBY), 256, syrk_smem>>>(0);

    reduceG2_kernel<<<dim3(3, 64), 256>>>();

    static const int chol_smem = (C * (C + 1) / 2) * (int)sizeof(float);  // 131584
    cudaFuncSetAttribute(chol_kernel, cudaFuncAttributeMaxDynamicSharedMemorySize, chol_smem);
    chol_kernel<<<1, 256, chol_smem>>>(rows);

    static const int wh_smem = 131072;
    cudaFuncSetAttribute(whiten_mma, cudaFuncAttributeMaxDynamicSharedMemorySize, wh_smem);
    whiten_mma<<<rows / 128, 512, wh_smem>>>(x, out);
}

// round 5
// speedup vs baseline: 2.3177x; 1.5946x over previous
#include <cuda_runtime.h>
#include <cuda_bf16.h>
#include <math.h>
#include <stdint.h>

#define C 256
#define ROWS 131072
#define EPS 0.001f
#define NSPLIT 2048
#define NBY 128              // syrk split-K blocks
#define SY_NCH 32            // chunks per syrk block (1024/32)
#define WH_NCH 8             // whiten k-chunks (256/32)

// ---------------- scratch ----------------
__device__ __nv_bfloat16 g_xhT[(size_t)C * ROWS];   // transposed hi plane [ch][row]
__device__ __nv_bfloat16 g_xlT[(size_t)C * ROWS];   // transposed lo plane
__device__ __nv_bfloat16 g_xh[(size_t)ROWS * C];    // row-major hi plane [row][ch]
__device__ __nv_bfloat16 g_xl[(size_t)ROWS * C];    // row-major lo plane
__device__ float g_psum[NSPLIT * C];
__device__ float g_psum2[16 * C];
__device__ float g_pG2[(size_t)3 * NBY * 128 * 128];
__device__ float g_G[C * C];
__device__ float g_W[C * C];
__device__ float g_bias[C];
__device__ __nv_bfloat16 g_Whi[C * C];
__device__ __nv_bfloat16 g_Wlo[C * C];

__constant__ int c2_pi[3] = {0, 0, 1};
__constant__ int c2_pj[3] = {0, 1, 1};

// ---------------- helpers ----------------
__device__ __forceinline__ uint32_t smem_u32(const void* p) {
    uint32_t a;
    asm("{ .reg .u64 t; cvta.to.shared.u64 t, %1; cvt.u32.u64 %0, t; }" : "=r"(a) : "l"(p));
    return a;
}
__device__ __forceinline__ void cp16(uint32_t dst, const void* src) {
    asm volatile("cp.async.cg.shared.global [%0], [%1], 16;" :: "r"(dst), "l"(src));
}
#define CP_COMMIT() asm volatile("cp.async.commit_group;" ::: "memory")
#define CP_WAIT1()  asm volatile("cp.async.wait_group 1;" ::: "memory")
#define CP_WAIT0()  asm volatile("cp.async.wait_group 0;" ::: "memory")

__device__ __forceinline__ void mma_bf16(float* d, const uint32_t* a, const uint32_t* b) {
    asm volatile(
        "mma.sync.aligned.m16n8k16.row.col.f32.bf16.bf16.f32 "
        "{%0,%1,%2,%3}, {%4,%5,%6,%7}, {%8,%9}, {%0,%1,%2,%3};\n"
        : "+f"(d[0]), "+f"(d[1]), "+f"(d[2]), "+f"(d[3])
        : "r"(a[0]), "r"(a[1]), "r"(a[2]), "r"(a[3]), "r"(b[0]), "r"(b[1]));
}
__device__ __forceinline__ void ldsm4(uint32_t& d0, uint32_t& d1, uint32_t& d2, uint32_t& d3,
                                      uint32_t a) {
    asm volatile("ldmatrix.sync.aligned.m8n8.x4.shared.b16 {%0,%1,%2,%3}, [%4];"
                 : "=r"(d0), "=r"(d1), "=r"(d2), "=r"(d3) : "r"(a));
}
__device__ __forceinline__ uint32_t pack2(__nv_bfloat16 lo, __nv_bfloat16 hi) {
    return (uint32_t)__bfloat16_as_ushort(lo) | ((uint32_t)__bfloat16_as_ushort(hi) << 16);
}
// bank-conflict-free 16B piece placement within an 8KB.. region of [row][2 pieces]
__device__ __forceinline__ uint32_t sw16(int row, int pp) {
    return ((uint32_t)(((row << 1) | pp) ^ ((row >> 2) & 1))) << 4;
}

// ---------------- 1) split x -> 4 bf16 planes + channel sums ----------------
__global__ __launch_bounds__(256) void split_kernel(const float* __restrict__ x) {
    __shared__ float stage[64][261];
    __shared__ float csum[4][C];
    int tid = threadIdx.x;
    size_t r0 = (size_t)blockIdx.x * 64;
    int c4 = tid & 63, rr = tid >> 6;
    uint32_t* rH = (uint32_t*)g_xh;
    uint32_t* rL = (uint32_t*)g_xl;
    float s0 = 0, s1 = 0, s2 = 0, s3 = 0;
#pragma unroll 4
    for (int i = 0; i < 16; ++i) {
        int r = 4 * i + rr;
        float4 v = *(const float4*)(x + (r0 + r) * C + c4 * 4);
        stage[r][c4 * 4 + 0] = v.x; stage[r][c4 * 4 + 1] = v.y;
        stage[r][c4 * 4 + 2] = v.z; stage[r][c4 * 4 + 3] = v.w;
        s0 += v.x; s1 += v.y; s2 += v.z; s3 += v.w;
        // row-major planes
        __nv_bfloat16 h0 = __float2bfloat16_rn(v.x), h1 = __float2bfloat16_rn(v.y);
        __nv_bfloat16 h2 = __float2bfloat16_rn(v.z), h3 = __float2bfloat16_rn(v.w);
        __nv_bfloat16 l0 = __float2bfloat16_rn(v.x - __bfloat162float(h0));
        __nv_bfloat16 l1 = __float2bfloat16_rn(v.y - __bfloat162float(h1));
        __nv_bfloat16 l2 = __float2bfloat16_rn(v.z - __bfloat162float(h2));
        __nv_bfloat16 l3 = __float2bfloat16_rn(v.w - __bfloat162float(h3));
        size_t d = ((r0 + r) * C + c4 * 4) >> 1;
        rH[d] = pack2(h0, h1); rH[d + 1] = pack2(h2, h3);
        rL[d] = pack2(l0, l1); rL[d + 1] = pack2(l2, l3);
    }
    csum[rr][c4 * 4 + 0] = s0; csum[rr][c4 * 4 + 1] = s1;
    csum[rr][c4 * 4 + 2] = s2; csum[rr][c4 * 4 + 3] = s3;
    __syncthreads();
    if (tid < C)
        g_psum[blockIdx.x * C + tid] = csum[0][tid] + csum[1][tid] + csum[2][tid] + csum[3][tid];

    int r2 = tid & 31, chb = tid >> 5;
    uint32_t* dH = (uint32_t*)g_xhT;
    uint32_t* dL = (uint32_t*)g_xlT;
    size_t rbase = r0 >> 1;
#pragma unroll 4
    for (int k = 0; k < 32; ++k) {
        int ch = chb + 8 * k;
        float f0 = stage[2 * r2][ch], f1 = stage[2 * r2 + 1][ch];
        __nv_bfloat16 h0 = __float2bfloat16_rn(f0), h1 = __float2bfloat16_rn(f1);
        __nv_bfloat16 l0 = __float2bfloat16_rn(f0 - __bfloat162float(h0));
        __nv_bfloat16 l1 = __float2bfloat16_rn(f1 - __bfloat162float(h1));
        dH[(size_t)ch * (ROWS / 2) + rbase + r2] = pack2(h0, h1);
        dL[(size_t)ch * (ROWS / 2) + rbase + r2] = pack2(l0, l1);
    }
}

__global__ __launch_bounds__(256) void psum_reduce() {
    float s = 0.f;
    int b0 = blockIdx.x * 128;
#pragma unroll 8
    for (int i = 0; i < 128; ++i) s += g_psum[(b0 + i) * C + threadIdx.x];
    g_psum2[blockIdx.x * C + threadIdx.x] = s;
}

// ---------------- 2) SYRK: 128x128 tile pairs, cp.async + ldmatrix + mma ----------------
// smem: stage(2) x tile t {AH,AL,BH,BL} 8KB each = [slab2][128 rows][2x16B swizzled]
__global__ __launch_bounds__(256, 2) void syrk_mma() {
    extern __shared__ char smem[];
    uint32_t sb = smem_u32(smem);

    int tid = threadIdx.x, lane = tid & 31, warp = tid >> 5;
    int wm = warp >> 2, wn = warp & 3;          // 2x4 warps, warp tile 64x32
    int g4 = lane >> 2, t4 = lane & 3;
    int lrow = lane & 15, lpp = lane >> 4;
    int p = blockIdx.x;
    int ti = c2_pi[p], tj = c2_pj[p];
    size_t k0base = (size_t)blockIdx.y * (ROWS / NBY);

    float acc[4][4][4];
#pragma unroll
    for (int a = 0; a < 4; ++a)
#pragma unroll
        for (int b = 0; b < 4; ++b)
#pragma unroll
            for (int r = 0; r < 4; ++r) acc[a][b][r] = 0.f;

    auto issue = [&](int cc, int s) {
        size_t k0 = k0base + (size_t)cc * 32;
#pragma unroll
        for (int q = 0; q < 8; ++q) {
            int idx = tid + 256 * q;            // 0..2047
            int t = idx >> 9;                   // AH AL BH BL
            int ch = (idx >> 2) & 127;
            int pc = idx & 3;                   // 16B piece: slab=pc>>1, pp=pc&1
            const __nv_bfloat16* plane = (t & 1) ? g_xlT : g_xhT;
            int cb = ((t < 2) ? ti : tj) * 128;
            const void* src = plane + (size_t)(cb + ch) * ROWS + k0 + pc * 8;
            uint32_t dst = sb + (uint32_t)s * 32768 + (uint32_t)t * 8192 +
                           (uint32_t)(pc >> 1) * 4096 + sw16(ch, pc & 1);
            cp16(dst, src);
        }
    };

    issue(0, 0); CP_COMMIT();
    for (int c = 0; c < SY_NCH; ++c) {
        int s = c & 1;
        __syncthreads();
        if (c + 1 < SY_NCH) { issue(c + 1, s ^ 1); CP_COMMIT(); CP_WAIT1(); }
        else CP_WAIT0();
        __syncthreads();

        uint32_t stg = sb + (uint32_t)s * 32768;
#pragma unroll
        for (int ks = 0; ks < 2; ++ks) {
            uint32_t AH = stg + (uint32_t)ks * 4096;
            uint32_t AL = AH + 8192, BH = AH + 16384, BL = AH + 24576;
            uint32_t bh[4][2], bl[4][2];
#pragma unroll
            for (int np = 0; np < 2; ++np) {
                int nr = wn * 32 + np * 16 + lrow;
                ldsm4(bh[np * 2][0], bh[np * 2 + 1][0], bh[np * 2][1], bh[np * 2 + 1][1],
                      BH + sw16(nr, lpp));
                ldsm4(bl[np * 2][0], bl[np * 2 + 1][0], bl[np * 2][1], bl[np * 2 + 1][1],
                      BL + sw16(nr, lpp));
            }
#pragma unroll
            for (int mf = 0; mf < 4; ++mf) {
                int mr = wm * 64 + mf * 16 + lrow;
                uint32_t ah[4], al[4];
                ldsm4(ah[0], ah[1], ah[2], ah[3], AH + sw16(mr, lpp));
                ldsm4(al[0], al[1], al[2], al[3], AL + sw16(mr, lpp));
#pragma unroll
                for (int nf = 0; nf < 4; ++nf) {
                    mma_bf16(acc[mf][nf], ah, bh[nf]);
                    mma_bf16(acc[mf][nf], ah, bl[nf]);
                    mma_bf16(acc[mf][nf], al, bh[nf]);
                }
            }
        }
    }

    float* dst = g_pG2 + ((size_t)p * NBY + blockIdx.y) * 16384;
#pragma unroll
    for (int mf = 0; mf < 4; ++mf)
#pragma unroll
        for (int nf = 0; nf < 4; ++nf) {
            int r = wm * 64 + mf * 16 + g4;
            int cc = wn * 32 + nf * 8 + t4 * 2;
            dst[r * 128 + cc]           = acc[mf][nf][0];
            dst[r * 128 + cc + 1]       = acc[mf][nf][1];
            dst[(r + 8) * 128 + cc]     = acc[mf][nf][2];
            dst[(r + 8) * 128 + cc + 1] = acc[mf][nf][3];
        }
}

// ---------------- 3) deterministic reduction ----------------
__global__ __launch_bounds__(256) void reduceG2_kernel() {
    int p = blockIdx.x;
    int e = blockIdx.y * 256 + threadIdx.x;   // 0..16383
    const float* src = g_pG2 + (size_t)p * NBY * 16384 + e;
    float s = 0.f;
#pragma unroll 8
    for (int c = 0; c < NBY; ++c) s += src[(size_t)c * 16384];
    int a = e >> 7, b = e & 127;
    int gi = c2_pi[p] * 128 + a, gj = c2_pj[p] * 128 + b;
    g_G[gi * C + gj] = s;
    g_G[gj * C + gi] = s;
}

// ---------------- 4) mean + blocked Cholesky + blocked L^{-1} + bias + W split ----------------
extern "C" __global__ __launch_bounds__(256) void chol_kernel(int rows) {
    extern __shared__ float Lp[];     // packed lower tri, 32896 floats
    __shared__ float m[C];
    __shared__ float scrD[32 * 33];
    __shared__ float sdinv[32];
    __shared__ float scr[32 * 32];
    int tid = threadIdx.x, lane = tid & 31, warp = tid >> 5;

    {
        float s = 0.f;
#pragma unroll
        for (int b = 0; b < 16; ++b) s += g_psum2[b * C + tid];
        m[tid] = s / (float)rows;
    }
    __syncthreads();

    const int TOT = C * (C + 1) / 2;
    float scale = (1.f - EPS) / (float)(rows - 1);
    for (int idx = tid; idx < TOT; idx += 256) {
        int i = (int)((sqrtf(8.f * (float)idx + 1.f) - 1.f) * 0.5f);
        while ((i + 1) * (i + 2) / 2 <= idx) ++i;
        while (i * (i + 1) / 2 > idx) --i;
        int j = idx - i * (i + 1) / 2;
        float v = (g_G[i * C + j] - (float)rows * m[i] * m[j]) * scale;
        if (i == j) v += EPS;
        Lp[idx] = v;
    }
    __syncthreads();

    // ---- blocked Cholesky, panel width 32 ----
    for (int pb = 0; pb < 8; ++pb) {
        int base = pb * 32;
        // copy diag block
        for (int idx = tid; idx < 1024; idx += 256) {
            int i = idx >> 5, j = idx & 31;
            int gi = base + i;
            scrD[i * 33 + j] = (j <= i) ? Lp[gi * (gi + 1) / 2 + base + j] : 0.f;
        }
        __syncthreads();
        // warp 0: factor 32x32 diag in shared
        if (warp == 0) {
            for (int k = 0; k < 32; ++k) {
                if (lane == 0) scrD[k * 33 + k] = sqrtf(scrD[k * 33 + k]);
                __syncwarp();
                float inv = 1.f / scrD[k * 33 + k];
                if (lane > k) scrD[lane * 33 + k] *= inv;
                __syncwarp();
                if (lane > k) {
                    float lik = scrD[lane * 33 + k];
                    for (int j = k + 1; j <= lane; ++j)
                        scrD[lane * 33 + j] -= lik * scrD[j * 33 + k];
                }
                __syncwarp();
            }
        }
        __syncthreads();
        if (tid < 32) sdinv[tid] = 1.f / scrD[tid * 33 + tid];
        // write back diag
        for (int idx = tid; idx < 1024; idx += 256) {
            int i = idx >> 5, j = idx & 31;
            if (j <= i) {
                int gi = base + i;
                Lp[gi * (gi + 1) / 2 + base + j] = scrD[i * 33 + j];
            }
        }
        __syncthreads();
        int R = 256 - base - 32;
        // TRSM: rows below panel
        if (tid < R) {
            int gi = base + 32 + tid;
            int ro = gi * (gi + 1) / 2 + base;
            float r[32];
#pragma unroll
            for (int t = 0; t < 32; ++t) r[t] = Lp[ro + t];
#pragma unroll
            for (int k = 0; k < 32; ++k) {
                float s = r[k];
                for (int t = 0; t < k; ++t) s -= r[t] * scrD[k * 33 + t];
                r[k] = s * sdinv[k];
            }
#pragma unroll
            for (int t = 0; t < 32; ++t) Lp[ro + t] = r[t];
        }
        __syncthreads();
        // trailing SYRK update: A[i][j] -= P[i]·P[j]
        if (R > 0) {
            int ti2 = tid >> 3, tj2 = tid & 7;
            for (int rt = 0; rt * 32 < R; ++rt) {
                int gi = base + 32 + rt * 32 + ti2;
                if (gi < 256) {
                    int roI = gi * (gi + 1) / 2;
                    float pi[32];
#pragma unroll
                    for (int t = 0; t < 32; ++t) pi[t] = Lp[roI + base + t];
                    for (int j0 = base + 32 + tj2 * 4; j0 <= gi; j0 += 32) {
                        int j1 = min(j0 + 1, 255), j2 = min(j0 + 2, 255), j3 = min(j0 + 3, 255);
                        int ro0 = j0 * (j0 + 1) / 2 + base;
                        int ro1 = j1 * (j1 + 1) / 2 + base;
                        int ro2 = j2 * (j2 + 1) / 2 + base;
                        int ro3 = j3 * (j3 + 1) / 2 + base;
                        float a0 = 0, a1 = 0, a2 = 0, a3 = 0;
#pragma unroll
                        for (int t = 0; t < 32; ++t) {
                            float pv = pi[t];
                            a0 += pv * Lp[ro0 + t];
                            a1 += pv * Lp[ro1 + t];
                            a2 += pv * Lp[ro2 + t];
                            a3 += pv * Lp[ro3 + t];
                        }
                        Lp[roI + j0] -= a0;
                        if (j0 + 1 <= gi) Lp[roI + j0 + 1] -= a1;
                        if (j0 + 2 <= gi) Lp[roI + j0 + 2] -= a2;
                        if (j0 + 3 <= gi) Lp[roI + j0 + 3] -= a3;
                    }
                }
            }
        }
        __syncthreads();
    }

    // ---- blocked inversion: diagonal 32x32 blocks in registers ----
    {
        int b = tid >> 5, j = tid & 31;
        int rb = b * 32;
        float w[32];
#pragma unroll
        for (int i = 0; i < 32; ++i) {
            float s = (i == j) ? 1.f : 0.f;
            const float* lrow = &Lp[(rb + i) * (rb + i + 1) / 2 + rb];
#pragma unroll
            for (int k = 0; k < 32; ++k)
                if (k < i) s -= lrow[k] * w[k];
            w[i] = (i >= j) ? s / lrow[i] : 0.f;
        }
#pragma unroll
        for (int i = 0; i < 32; ++i) g_W[(rb + i) * C + rb + j] = w[i];
    }
    __syncthreads();
    for (int idx = tid; idx < C * C; idx += 256) {
        int r = idx >> 8, cc = idx & 255;
        if (cc > r) g_W[idx] = 0.f;
    }
    __syncthreads();

    // off-diagonal blocks
    {
        int r = tid >> 3, c4 = (tid & 7) * 4;
        for (int step = 1; step < 8; ++step) {
            for (int bj = 0; bj + step < 8; ++bj) {
                int bi = bj + step;
                float a0 = 0, a1 = 0, a2 = 0, a3 = 0;
                const float* lrow = &Lp[(bi * 32 + r) * (bi * 32 + r + 1) / 2];
                for (int kb = bj; kb < bi; ++kb) {
#pragma unroll 8
                    for (int kk = 0; kk < 32; ++kk) {
                        float lv = lrow[kb * 32 + kk];
                        const float* wr = &g_W[(kb * 32 + kk) * C + bj * 32 + c4];
                        a0 += lv * wr[0]; a1 += lv * wr[1]; a2 += lv * wr[2]; a3 += lv * wr[3];
                    }
                }
                scr[r * 32 + c4 + 0] = a0; scr[r * 32 + c4 + 1] = a1;
                scr[r * 32 + c4 + 2] = a2; scr[r * 32 + c4 + 3] = a3;
                __syncthreads();
                float o0 = 0, o1 = 0, o2 = 0, o3 = 0;
#pragma unroll 8
                for (int kk = 0; kk < 32; ++kk) {
                    float dv = g_W[(bi * 32 + r) * C + bi * 32 + kk];
                    o0 += dv * scr[kk * 32 + c4 + 0];
                    o1 += dv * scr[kk * 32 + c4 + 1];
                    o2 += dv * scr[kk * 32 + c4 + 2];
                    o3 += dv * scr[kk * 32 + c4 + 3];
                }
                g_W[(bi * 32 + r) * C + bj * 32 + c4 + 0] = -o0;
                g_W[(bi * 32 + r) * C + bj * 32 + c4 + 1] = -o1;
                g_W[(bi * 32 + r) * C + bj * 32 + c4 + 2] = -o2;
                g_W[(bi * 32 + r) * C + bj * 32 + c4 + 3] = -o3;
                __syncthreads();
            }
        }
    }

    {
        float s = 0.f;
#pragma unroll 4
        for (int j = 0; j <= tid; ++j) s += g_W[tid * C + j] * m[j];
        g_bias[tid] = s;
    }

    for (int idx = tid; idx < C * C; idx += 256) {
        float w = g_W[idx];
        __nv_bfloat16 h = __float2bfloat16_rn(w);
        g_Whi[idx] = h;
        g_Wlo[idx] = __float2bfloat16_rn(w - __bfloat162float(h));
    }
}

// ---------------- 5) whitening: out = x W^T - bias (planes + ldmatrix + mma) ----------------
// stage (48KB x2): A {H,L} 8KB each: [slab2][128][2x16B sw]; B {H,L} 16KB each: [slab2][256][2x16B sw]
__global__ __launch_bounds__(512, 1) void whiten_mma(float* __restrict__ out) {
    extern __shared__ char smem[];
    __shared__ float sbias[C];
    uint32_t sb = smem_u32(smem);

    int tid = threadIdx.x, lane = tid & 31, warp = tid >> 5;
    int wm = warp >> 2, wn = warp & 3;      // 4x4 warps, warp tile 32x64
    int g4 = lane >> 2, t4 = lane & 3;
    int lrow = lane & 15, lpp = lane >> 4;
    size_t m0 = (size_t)blockIdx.x * 128;

    if (tid < C) sbias[tid] = g_bias[tid];

    float acc[2][8][4];
#pragma unroll
    for (int a = 0; a < 2; ++a)
#pragma unroll
        for (int b = 0; b < 8; ++b)
#pragma unroll
            for (int r = 0; r < 4; ++r) acc[a][b][r] = 0.f;

    auto issue = [&](int cc, int s) {
        int k0 = cc * 32;
        // A planes: 1024 x 16B
#pragma unroll
        for (int q = 0; q < 2; ++q) {
            int idx = tid * 2 + q;
            int pl = idx >> 9, rem = idx & 511;
            int row = rem >> 2, sl = (rem >> 1) & 1, pp = rem & 1;
            const __nv_bfloat16* plane = pl ? g_xl : g_xh;
            cp16(sb + (uint32_t)s * 49152 + (uint32_t)pl * 8192 + (uint32_t)sl * 4096 +
                     sw16(row, pp),
                 plane + (m0 + row) * C + k0 + sl * 16 + pp * 8);
        }
        // B planes: 2048 x 16B
#pragma unroll
        for (int q = 0; q < 4; ++q) {
            int idx = tid + 512 * q;
            int pl = idx >> 10, rem = idx & 1023;
            int n = rem >> 2, sl = (rem >> 1) & 1, pp = rem & 1;
            const __nv_bfloat16* plane = pl ? g_Wlo : g_Whi;
            cp16(sb + (uint32_t)s * 49152 + 16384u + (uint32_t)pl * 16384 + (uint32_t)sl * 8192 +
                     sw16(n, pp),
                 plane + (size_t)n * C + k0 + sl * 16 + pp * 8);
        }
    };

    issue(0, 0); CP_COMMIT();
    for (int c = 0; c < WH_NCH; ++c) {
        int s = c & 1;
        __syncthreads();
        if (c + 1 < WH_NCH) { issue(c + 1, s ^ 1); CP_COMMIT(); CP_WAIT1(); }
        else CP_WAIT0();
        __syncthreads();

        uint32_t stg = sb + (uint32_t)s * 49152;
#pragma unroll
        for (int ks = 0; ks < 2; ++ks) {
            uint32_t XH = stg + (uint32_t)ks * 4096;
            uint32_t XL = XH + 8192;
            uint32_t WHb = stg + 16384u + (uint32_t)ks * 8192;
            uint32_t WLb = WHb + 16384;
            uint32_t bh[8][2], bl[8][2];
#pragma unroll
            for (int np = 0; np < 4; ++np) {
                int nr = wn * 64 + np * 16 + lrow;
                ldsm4(bh[np * 2][0], bh[np * 2 + 1][0], bh[np * 2][1], bh[np * 2 + 1][1],
                      WHb + sw16(nr, lpp));
                ldsm4(bl[np * 2][0], bl[np * 2 + 1][0], bl[np * 2][1], bl[np * 2 + 1][1],
                      WLb + sw16(nr, lpp));
            }
#pragma unroll
            for (int mf = 0; mf < 2; ++mf) {
                int mr = wm * 32 + mf * 16 + lrow;
                uint32_t ah[4], al[4];
                ldsm4(ah[0], ah[1], ah[2], ah[3], XH + sw16(mr, lpp));
                ldsm4(al[0], al[1], al[2], al[3], XL + sw16(mr, lpp));
#pragma unroll
                for (int nf = 0; nf < 8; ++nf) {
                    mma_bf16(acc[mf][nf], ah, bh[nf]);
                    mma_bf16(acc[mf][nf], ah, bl[nf]);
                    mma_bf16(acc[mf][nf], al, bh[nf]);
                }
            }
        }
    }

    // epilogue
#pragma unroll
    for (int mf = 0; mf < 2; ++mf)
#pragma unroll
        for (int nf = 0; nf < 8; ++nf) {
            int r = wm * 32 + mf * 16 + g4;
            int cc = wn * 64 + nf * 8 + t4 * 2;
            float b0 = sbias[cc], b1 = sbias[cc + 1];
            *(float2*)&out[(m0 + r) * C + cc]     = make_float2(acc[mf][nf][0] - b0, acc[mf][nf][1] - b1);
            *(float2*)&out[(m0 + r + 8) * C + cc] = make_float2(acc[mf][nf][2] - b0, acc[mf][nf][3] - b1);
        }
}

// ---------------- launch ----------------
extern "C" void kernel_launch(void* const* d_in, const int* in_sizes, int n_in,
                              void* d_out, int out_size) {
    const float* x = (const float*)d_in[0];
    float* out = (float*)d_out;
    int rows = in_sizes[0] / C;          // 131072

    split_kernel<<<NSPLIT, 256>>>(x);
    psum_reduce<<<16, 256>>>();

    static const int syrk_smem = 65536;
    cudaFuncSetAttribute(syrk_mma, cudaFuncAttributeMaxDynamicSharedMemorySize, syrk_smem);
    syrk_mma<<<dim3(3, NBY), 256, syrk_smem>>>();

    reduceG2_kernel<<<dim3(3, 64), 256>>>();

    static const int chol_smem = (C * (C + 1) / 2) * (int)sizeof(float);  // 131584
    cudaFuncSetAttribute(chol_kernel, cudaFuncAttributeMaxDynamicSharedMemorySize, chol_smem);
    chol_kernel<<<1, 256, chol_smem>>>(rows);

    static const int wh_smem = 98304;
    cudaFuncSetAttribute(whiten_mma, cudaFuncAttributeMaxDynamicSharedMemorySize, wh_smem);
    whiten_mma<<<rows / 128, 512, wh_smem>>>(out);
}

// round 7
// speedup vs baseline: 2.4306x; 1.0487x over previous
#include <cuda_runtime.h>
#include <cuda_bf16.h>
#include <math.h>
#include <stdint.h>

#define C 256
#define ROWS 131072
#define EPS 0.001f
#define NSPLIT 2048
#define NBY 128              // syrk split-K blocks
#define SY_NCH 32            // chunks per syrk block (1024/32)
#define WH_NCH 8             // whiten k-chunks (256/32)

// ---------------- scratch ----------------
__device__ __nv_bfloat16 g_xhT[(size_t)C * ROWS];   // transposed hi plane [ch][row]
__device__ __nv_bfloat16 g_xlT[(size_t)C * ROWS];   // transposed lo plane
__device__ float g_psum[NSPLIT * C];
__device__ float g_psum2[16 * C];
__device__ float g_pG2[(size_t)3 * NBY * 128 * 128];
__device__ float g_G[C * C];
__device__ float g_W[C * C];
__device__ float g_bias[C];
__device__ __nv_bfloat16 g_Whi[C * C];
__device__ __nv_bfloat16 g_Wlo[C * C];

__constant__ int c2_pi[3] = {0, 0, 1};
__constant__ int c2_pj[3] = {0, 1, 1};

// ---------------- helpers ----------------
__device__ __forceinline__ uint32_t smem_u32(const void* p) {
    uint32_t a;
    asm("{ .reg .u64 t; cvta.to.shared.u64 t, %1; cvt.u32.u64 %0, t; }" : "=r"(a) : "l"(p));
    return a;
}
__device__ __forceinline__ void cp16(uint32_t dst, const void* src) {
    asm volatile("cp.async.cg.shared.global [%0], [%1], 16;" :: "r"(dst), "l"(src));
}
#define CP_COMMIT() asm volatile("cp.async.commit_group;" ::: "memory")
#define CP_WAIT1()  asm volatile("cp.async.wait_group 1;" ::: "memory")
#define CP_WAIT0()  asm volatile("cp.async.wait_group 0;" ::: "memory")

__device__ __forceinline__ void mma_bf16(float* d, const uint32_t* a, const uint32_t* b) {
    asm volatile(
        "mma.sync.aligned.m16n8k16.row.col.f32.bf16.bf16.f32 "
        "{%0,%1,%2,%3}, {%4,%5,%6,%7}, {%8,%9}, {%0,%1,%2,%3};\n"
        : "+f"(d[0]), "+f"(d[1]), "+f"(d[2]), "+f"(d[3])
        : "r"(a[0]), "r"(a[1]), "r"(a[2]), "r"(a[3]), "r"(b[0]), "r"(b[1]));
}
__device__ __forceinline__ void ldsm4(uint32_t& d0, uint32_t& d1, uint32_t& d2, uint32_t& d3,
                                      uint32_t a) {
    asm volatile("ldmatrix.sync.aligned.m8n8.x4.shared.b16 {%0,%1,%2,%3}, [%4];"
                 : "=r"(d0), "=r"(d1), "=r"(d2), "=r"(d3) : "r"(a));
}
__device__ __forceinline__ uint32_t pack2(__nv_bfloat16 lo, __nv_bfloat16 hi) {
    return (uint32_t)__bfloat16_as_ushort(lo) | ((uint32_t)__bfloat16_as_ushort(hi) << 16);
}
// bank-conflict-free 16B piece placement within 8KB plane of [row][2 pieces]
__device__ __forceinline__ uint32_t sw16(int row, int pp) {
    return ((uint32_t)(((row << 1) | pp) ^ ((row >> 2) & 1))) << 4;
}
__device__ __forceinline__ void split8(const float* f, uint4& H, uint4& L) {
    __nv_bfloat16 h[8], l[8];
#pragma unroll
    for (int e = 0; e < 8; ++e) {
        h[e] = __float2bfloat16_rn(f[e]);
        l[e] = __float2bfloat16_rn(f[e] - __bfloat162float(h[e]));
    }
    H = make_uint4(pack2(h[0], h[1]), pack2(h[2], h[3]), pack2(h[4], h[5]), pack2(h[6], h[7]));
    L = make_uint4(pack2(l[0], l[1]), pack2(l[2], l[3]), pack2(l[4], l[5]), pack2(l[6], l[7]));
}

// ---------------- 1) split x -> transposed bf16 hi/lo planes + channel sums ----------------
__global__ __launch_bounds__(256) void split_kernel(const float* __restrict__ x) {
    __shared__ float stage[64][261];
    __shared__ float csum[4][C];
    int tid = threadIdx.x;
    size_t r0 = (size_t)blockIdx.x * 64;
    int c4 = tid & 63, rr = tid >> 6;
    float s0 = 0, s1 = 0, s2 = 0, s3 = 0;
#pragma unroll 4
    for (int i = 0; i < 16; ++i) {
        int r = 4 * i + rr;
        float4 v = *(const float4*)(x + (r0 + r) * C + c4 * 4);
        stage[r][c4 * 4 + 0] = v.x; stage[r][c4 * 4 + 1] = v.y;
        stage[r][c4 * 4 + 2] = v.z; stage[r][c4 * 4 + 3] = v.w;
        s0 += v.x; s1 += v.y; s2 += v.z; s3 += v.w;
    }
    csum[rr][c4 * 4 + 0] = s0; csum[rr][c4 * 4 + 1] = s1;
    csum[rr][c4 * 4 + 2] = s2; csum[rr][c4 * 4 + 3] = s3;
    __syncthreads();
    if (tid < C)
        g_psum[blockIdx.x * C + tid] = csum[0][tid] + csum[1][tid] + csum[2][tid] + csum[3][tid];

    int r2 = tid & 31, chb = tid >> 5;
    uint32_t* dH = (uint32_t*)g_xhT;
    uint32_t* dL = (uint32_t*)g_xlT;
    size_t rbase = r0 >> 1;
#pragma unroll 4
    for (int k = 0; k < 32; ++k) {
        int ch = chb + 8 * k;
        float f0 = stage[2 * r2][ch], f1 = stage[2 * r2 + 1][ch];
        __nv_bfloat16 h0 = __float2bfloat16_rn(f0), h1 = __float2bfloat16_rn(f1);
        __nv_bfloat16 l0 = __float2bfloat16_rn(f0 - __bfloat162float(h0));
        __nv_bfloat16 l1 = __float2bfloat16_rn(f1 - __bfloat162float(h1));
        dH[(size_t)ch * (ROWS / 2) + rbase + r2] = pack2(h0, h1);
        dL[(size_t)ch * (ROWS / 2) + rbase + r2] = pack2(l0, l1);
    }
}

__global__ __launch_bounds__(256) void psum_reduce() {
    float s = 0.f;
    int b0 = blockIdx.x * 128;
#pragma unroll 8
    for (int i = 0; i < 128; ++i) s += g_psum[(b0 + i) * C + threadIdx.x];
    g_psum2[blockIdx.x * C + threadIdx.x] = s;
}

// ---------------- 2) SYRK: 128x128 tile pairs, cp.async + ldmatrix + mma (R5-proven) ----------------
__global__ __launch_bounds__(256, 2) void syrk_mma() {
    extern __shared__ char smem[];
    uint32_t sb = smem_u32(smem);

    int tid = threadIdx.x, lane = tid & 31, warp = tid >> 5;
    int wm = warp >> 2, wn = warp & 3;          // 2x4 warps, warp tile 64x32
    int g4 = lane >> 2, t4 = lane & 3;
    int lrow = lane & 15, lpp = lane >> 4;
    int p = blockIdx.x;
    int ti = c2_pi[p], tj = c2_pj[p];
    size_t k0base = (size_t)blockIdx.y * (ROWS / NBY);

    float acc[4][4][4];
#pragma unroll
    for (int a = 0; a < 4; ++a)
#pragma unroll
        for (int b = 0; b < 4; ++b)
#pragma unroll
            for (int r = 0; r < 4; ++r) acc[a][b][r] = 0.f;

    auto issue = [&](int cc, int s) {
        size_t k0 = k0base + (size_t)cc * 32;
#pragma unroll
        for (int q = 0; q < 8; ++q) {
            int idx = tid + 256 * q;            // 0..2047
            int t = idx >> 9;                   // AH AL BH BL
            int ch = (idx >> 2) & 127;
            int pc = idx & 3;                   // 16B piece: slab=pc>>1, pp=pc&1
            const __nv_bfloat16* plane = (t & 1) ? g_xlT : g_xhT;
            int cb = ((t < 2) ? ti : tj) * 128;
            const void* src = plane + (size_t)(cb + ch) * ROWS + k0 + pc * 8;
            uint32_t dst = sb + (uint32_t)s * 32768 + (uint32_t)t * 8192 +
                           (uint32_t)(pc >> 1) * 4096 + sw16(ch, pc & 1);
            cp16(dst, src);
        }
    };

    issue(0, 0); CP_COMMIT();
    for (int c = 0; c < SY_NCH; ++c) {
        int s = c & 1;
        __syncthreads();
        if (c + 1 < SY_NCH) { issue(c + 1, s ^ 1); CP_COMMIT(); CP_WAIT1(); }
        else CP_WAIT0();
        __syncthreads();

        uint32_t stg = sb + (uint32_t)s * 32768;
#pragma unroll
        for (int ks = 0; ks < 2; ++ks) {
            uint32_t AH = stg + (uint32_t)ks * 4096;
            uint32_t AL = AH + 8192, BH = AH + 16384, BL = AH + 24576;
            uint32_t bh[4][2], bl[4][2];
#pragma unroll
            for (int np = 0; np < 2; ++np) {
                int nr = wn * 32 + np * 16 + lrow;
                ldsm4(bh[np * 2][0], bh[np * 2 + 1][0], bh[np * 2][1], bh[np * 2 + 1][1],
                      BH + sw16(nr, lpp));
                ldsm4(bl[np * 2][0], bl[np * 2 + 1][0], bl[np * 2][1], bl[np * 2 + 1][1],
                      BL + sw16(nr, lpp));
            }
#pragma unroll
            for (int mf = 0; mf < 4; ++mf) {
                int mr = wm * 64 + mf * 16 + lrow;
                uint32_t ah[4], al[4];
                ldsm4(ah[0], ah[1], ah[2], ah[3], AH + sw16(mr, lpp));
                ldsm4(al[0], al[1], al[2], al[3], AL + sw16(mr, lpp));
#pragma unroll
                for (int nf = 0; nf < 4; ++nf) {
                    mma_bf16(acc[mf][nf], ah, bh[nf]);
                    mma_bf16(acc[mf][nf], ah, bl[nf]);
                    mma_bf16(acc[mf][nf], al, bh[nf]);
                }
            }
        }
    }

    float* dst = g_pG2 + ((size_t)p * NBY + blockIdx.y) * 16384;
#pragma unroll
    for (int mf = 0; mf < 4; ++mf)
#pragma unroll
        for (int nf = 0; nf < 4; ++nf) {
            int r = wm * 64 + mf * 16 + g4;
            int cc = wn * 32 + nf * 8 + t4 * 2;
            dst[r * 128 + cc]           = acc[mf][nf][0];
            dst[r * 128 + cc + 1]       = acc[mf][nf][1];
            dst[(r + 8) * 128 + cc]     = acc[mf][nf][2];
            dst[(r + 8) * 128 + cc + 1] = acc[mf][nf][3];
        }
}

// ---------------- 3) deterministic reduction ----------------
__global__ __launch_bounds__(256) void reduceG2_kernel() {
    int p = blockIdx.x;
    int e = blockIdx.y * 256 + threadIdx.x;   // 0..16383
    const float* src = g_pG2 + (size_t)p * NBY * 16384 + e;
    float s = 0.f;
#pragma unroll 8
    for (int c = 0; c < NBY; ++c) s += src[(size_t)c * 16384];
    int a = e >> 7, b = e & 127;
    int gi = c2_pi[p] * 128 + a, gj = c2_pj[p] * 128 + b;
    g_G[gi * C + gj] = s;
    g_G[gj * C + gi] = s;
}

// ---------------- 4) mean + blocked Cholesky + blocked L^{-1} + bias + W split ----------------
extern "C" __global__ __launch_bounds__(256) void chol_kernel(int rows) {
    extern __shared__ float Lp[];     // packed lower tri, 32896 floats
    __shared__ float m[C];
    __shared__ float scrD[32 * 33];
    __shared__ float sdinv[32];
    __shared__ float scr[32 * 32];
    int tid = threadIdx.x, lane = tid & 31, warp = tid >> 5;

    {
        float s = 0.f;
#pragma unroll
        for (int b = 0; b < 16; ++b) s += g_psum2[b * C + tid];
        m[tid] = s / (float)rows;
    }
    __syncthreads();

    const int TOT = C * (C + 1) / 2;
    float scale = (1.f - EPS) / (float)(rows - 1);
    for (int idx = tid; idx < TOT; idx += 256) {
        int i = (int)((sqrtf(8.f * (float)idx + 1.f) - 1.f) * 0.5f);
        while ((i + 1) * (i + 2) / 2 <= idx) ++i;
        while (i * (i + 1) / 2 > idx) --i;
        int j = idx - i * (i + 1) / 2;
        float v = (g_G[i * C + j] - (float)rows * m[i] * m[j]) * scale;
        if (i == j) v += EPS;
        Lp[idx] = v;
    }
    __syncthreads();

    // ---- blocked Cholesky, panel width 32 ----
    for (int pb = 0; pb < 8; ++pb) {
        int base = pb * 32;
        for (int idx = tid; idx < 1024; idx += 256) {
            int i = idx >> 5, j = idx & 31;
            int gi = base + i;
            scrD[i * 33 + j] = (j <= i) ? Lp[gi * (gi + 1) / 2 + base + j] : 0.f;
        }
        __syncthreads();
        if (warp == 0) {
            for (int k = 0; k < 32; ++k) {
                if (lane == 0) scrD[k * 33 + k] = sqrtf(scrD[k * 33 + k]);
                __syncwarp();
                float inv = 1.f / scrD[k * 33 + k];
                if (lane > k) scrD[lane * 33 + k] *= inv;
                __syncwarp();
                if (lane > k) {
                    float lik = scrD[lane * 33 + k];
                    for (int j = k + 1; j <= lane; ++j)
                        scrD[lane * 33 + j] -= lik * scrD[j * 33 + k];
                }
                __syncwarp();
            }
        }
        __syncthreads();
        if (tid < 32) sdinv[tid] = 1.f / scrD[tid * 33 + tid];
        for (int idx = tid; idx < 1024; idx += 256) {
            int i = idx >> 5, j = idx & 31;
            if (j <= i) {
                int gi = base + i;
                Lp[gi * (gi + 1) / 2 + base + j] = scrD[i * 33 + j];
            }
        }
        __syncthreads();
        int R = 256 - base - 32;
        if (tid < R) {
            int gi = base + 32 + tid;
            int ro = gi * (gi + 1) / 2 + base;
            float r[32];
#pragma unroll
            for (int t = 0; t < 32; ++t) r[t] = Lp[ro + t];
#pragma unroll
            for (int k = 0; k < 32; ++k) {
                float s = r[k];
                for (int t = 0; t < k; ++t) s -= r[t] * scrD[k * 33 + t];
                r[k] = s * sdinv[k];
            }
#pragma unroll
            for (int t = 0; t < 32; ++t) Lp[ro + t] = r[t];
        }
        __syncthreads();
        if (R > 0) {
            int ti2 = tid >> 3, tj2 = tid & 7;
            for (int rt = 0; rt * 32 < R; ++rt) {
                int gi = base + 32 + rt * 32 + ti2;
                if (gi < 256) {
                    int roI = gi * (gi + 1) / 2;
                    float pi[32];
#pragma unroll
                    for (int t = 0; t < 32; ++t) pi[t] = Lp[roI + base + t];
                    for (int j0 = base + 32 + tj2 * 4; j0 <= gi; j0 += 32) {
                        int j1 = min(j0 + 1, 255), j2 = min(j0 + 2, 255), j3 = min(j0 + 3, 255);
                        int ro0 = j0 * (j0 + 1) / 2 + base;
                        int ro1 = j1 * (j1 + 1) / 2 + base;
                        int ro2 = j2 * (j2 + 1) / 2 + base;
                        int ro3 = j3 * (j3 + 1) / 2 + base;
                        float a0 = 0, a1 = 0, a2 = 0, a3 = 0;
#pragma unroll
                        for (int t = 0; t < 32; ++t) {
                            float pv = pi[t];
                            a0 += pv * Lp[ro0 + t];
                            a1 += pv * Lp[ro1 + t];
                            a2 += pv * Lp[ro2 + t];
                            a3 += pv * Lp[ro3 + t];
                        }
                        Lp[roI + j0] -= a0;
                        if (j0 + 1 <= gi) Lp[roI + j0 + 1] -= a1;
                        if (j0 + 2 <= gi) Lp[roI + j0 + 2] -= a2;
                        if (j0 + 3 <= gi) Lp[roI + j0 + 3] -= a3;
                    }
                }
            }
        }
        __syncthreads();
    }

    // ---- blocked inversion: diagonal 32x32 blocks in registers ----
    {
        int b = tid >> 5, j = tid & 31;
        int rb = b * 32;
        float w[32];
#pragma unroll
        for (int i = 0; i < 32; ++i) {
            float s = (i == j) ? 1.f : 0.f;
            const float* lrow = &Lp[(rb + i) * (rb + i + 1) / 2 + rb];
#pragma unroll
            for (int k = 0; k < 32; ++k)
                if (k < i) s -= lrow[k] * w[k];
            w[i] = (i >= j) ? s / lrow[i] : 0.f;
        }
#pragma unroll
        for (int i = 0; i < 32; ++i) g_W[(rb + i) * C + rb + j] = w[i];
    }
    __syncthreads();
    for (int idx = tid; idx < C * C; idx += 256) {
        int r = idx >> 8, cc = idx & 255;
        if (cc > r) g_W[idx] = 0.f;
    }
    __syncthreads();

    // off-diagonal blocks
    {
        int r = tid >> 3, c4 = (tid & 7) * 4;
        for (int step = 1; step < 8; ++step) {
            for (int bj = 0; bj + step < 8; ++bj) {
                int bi = bj + step;
                float a0 = 0, a1 = 0, a2 = 0, a3 = 0;
                const float* lrow = &Lp[(bi * 32 + r) * (bi * 32 + r + 1) / 2];
                for (int kb = bj; kb < bi; ++kb) {
#pragma unroll 8
                    for (int kk = 0; kk < 32; ++kk) {
                        float lv = lrow[kb * 32 + kk];
                        const float* wr = &g_W[(kb * 32 + kk) * C + bj * 32 + c4];
                        a0 += lv * wr[0]; a1 += lv * wr[1]; a2 += lv * wr[2]; a3 += lv * wr[3];
                    }
                }
                scr[r * 32 + c4 + 0] = a0; scr[r * 32 + c4 + 1] = a1;
                scr[r * 32 + c4 + 2] = a2; scr[r * 32 + c4 + 3] = a3;
                __syncthreads();
                float o0 = 0, o1 = 0, o2 = 0, o3 = 0;
#pragma unroll 8
                for (int kk = 0; kk < 32; ++kk) {
                    float dv = g_W[(bi * 32 + r) * C + bi * 32 + kk];
                    o0 += dv * scr[kk * 32 + c4 + 0];
                    o1 += dv * scr[kk * 32 + c4 + 1];
                    o2 += dv * scr[kk * 32 + c4 + 2];
                    o3 += dv * scr[kk * 32 + c4 + 3];
                }
                g_W[(bi * 32 + r) * C + bj * 32 + c4 + 0] = -o0;
                g_W[(bi * 32 + r) * C + bj * 32 + c4 + 1] = -o1;
                g_W[(bi * 32 + r) * C + bj * 32 + c4 + 2] = -o2;
                g_W[(bi * 32 + r) * C + bj * 32 + c4 + 3] = -o3;
                __syncthreads();
            }
        }
    }

    {
        float s = 0.f;
#pragma unroll 4
        for (int j = 0; j <= tid; ++j) s += g_W[tid * C + j] * m[j];
        g_bias[tid] = s;
    }

    for (int idx = tid; idx < C * C; idx += 256) {
        float w = g_W[idx];
        __nv_bfloat16 h = __float2bfloat16_rn(w);
        g_Whi[idx] = h;
        g_Wlo[idx] = __float2bfloat16_rn(w - __bfloat162float(h));
    }
}

// ---------------- 5) whitening fused: x fp32 regs -> hi/lo planes -> mma ----------------
// smem: XH 8KB @0, XL 8KB @8192, W stages @16384: [s2][pl2][sl2][8KB] (64KB)
__global__ __launch_bounds__(512, 1) void whiten_fused(const float* __restrict__ x,
                                                       float* __restrict__ out) {
    extern __shared__ char smem[];
    __shared__ float sbias[C];
    uint32_t sb = smem_u32(smem);

    int tid = threadIdx.x, lane = tid & 31, warp = tid >> 5;
    int wm = warp >> 2, wn = warp & 3;      // 4x4 warps, warp tile 32x64
    int g4 = lane >> 2, t4 = lane & 3;
    int lrow = lane & 15, lpp = lane >> 4;
    size_t m0 = (size_t)blockIdx.x * 128;

    if (tid < C) sbias[tid] = g_bias[tid];

    float acc[2][8][4];
#pragma unroll
    for (int a = 0; a < 2; ++a)
#pragma unroll
        for (int b = 0; b < 8; ++b)
#pragma unroll
            for (int r = 0; r < 4; ++r) acc[a][b][r] = 0.f;

    int xrow = tid >> 2, xpp = tid & 3;
    const float* xp = x + (m0 + xrow) * C + xpp * 8;

    auto issueW = [&](int cc, int s) {
        int k0 = cc * 32;
#pragma unroll
        for (int q = 0; q < 4; ++q) {
            int idx = tid + 512 * q;
            int plm = idx >> 10, rem = idx & 1023;
            int n = rem >> 2, sl = (rem >> 1) & 1, pp = rem & 1;
            const __nv_bfloat16* plane = plm ? g_Wlo : g_Whi;
            cp16(sb + 16384u + (uint32_t)s * 32768 + (uint32_t)plm * 16384 +
                     (uint32_t)sl * 8192 + sw16(n, pp),
                 plane + (size_t)n * C + k0 + sl * 16 + pp * 8);
        }
    };

    float4 xv0 = *(const float4*)(xp);
    float4 xv1 = *(const float4*)(xp + 4);
    issueW(0, 0); CP_COMMIT();

    for (int c = 0; c < WH_NCH; ++c) {
        int s = c & 1;
        __syncthreads();   // prev MMA done reading X planes + W stage s^1
        // convert registers -> X planes
        {
            float f[8] = {xv0.x, xv0.y, xv0.z, xv0.w, xv1.x, xv1.y, xv1.z, xv1.w};
            uint4 H, L;
            split8(f, H, L);
            uint32_t off = (uint32_t)(xpp >> 1) * 4096 + sw16(xrow, xpp & 1);
            *(uint4*)(smem + off) = H;
            *(uint4*)(smem + 8192 + off) = L;
        }
        if (c + 1 < WH_NCH) {
            xv0 = *(const float4*)(xp + (c + 1) * 32);
            xv1 = *(const float4*)(xp + (c + 1) * 32 + 4);
            issueW(c + 1, s ^ 1); CP_COMMIT(); CP_WAIT1();
        } else CP_WAIT0();
        __syncthreads();

#pragma unroll
        for (int ks = 0; ks < 2; ++ks) {
            uint32_t XH = sb + (uint32_t)ks * 4096;
            uint32_t XL = XH + 8192;
            uint32_t WHb = sb + 16384u + (uint32_t)s * 32768 + (uint32_t)ks * 8192;
            uint32_t WLb = WHb + 16384;
            uint32_t bh[8][2], bl[8][2];
#pragma unroll
            for (int np = 0; np < 4; ++np) {
                int nr = wn * 64 + np * 16 + lrow;
                ldsm4(bh[np * 2][0], bh[np * 2 + 1][0], bh[np * 2][1], bh[np * 2 + 1][1],
                      WHb + sw16(nr, lpp));
                ldsm4(bl[np * 2][0], bl[np * 2 + 1][0], bl[np * 2][1], bl[np * 2 + 1][1],
                      WLb + sw16(nr, lpp));
            }
#pragma unroll
            for (int mf = 0; mf < 2; ++mf) {
                int mr = wm * 32 + mf * 16 + lrow;
                uint32_t ah[4], al[4];
                ldsm4(ah[0], ah[1], ah[2], ah[3], XH + sw16(mr, lpp));
                ldsm4(al[0], al[1], al[2], al[3], XL + sw16(mr, lpp));
#pragma unroll
                for (int nf = 0; nf < 8; ++nf) {
                    mma_bf16(acc[mf][nf], ah, bh[nf]);
                    mma_bf16(acc[mf][nf], ah, bl[nf]);
                    mma_bf16(acc[mf][nf], al, bh[nf]);
                }
            }
        }
    }

    // epilogue
#pragma unroll
    for (int mf = 0; mf < 2; ++mf)
#pragma unroll
        for (int nf = 0; nf < 8; ++nf) {
            int r = wm * 32 + mf * 16 + g4;
            int cc = wn * 64 + nf * 8 + t4 * 2;
            float b0 = sbias[cc], b1 = sbias[cc + 1];
            *(float2*)&out[(m0 + r) * C + cc]     = make_float2(acc[mf][nf][0] - b0, acc[mf][nf][1] - b1);
            *(float2*)&out[(m0 + r + 8) * C + cc] = make_float2(acc[mf][nf][2] - b0, acc[mf][nf][3] - b1);
        }
}

// ---------------- launch ----------------
extern "C" void kernel_launch(void* const* d_in, const int* in_sizes, int n_in,
                              void* d_out, int out_size) {
    const float* x = (const float*)d_in[0];
    float* out = (float*)d_out;
    int rows = in_sizes[0] / C;          // 131072

    split_kernel<<<NSPLIT, 256>>>(x);
    psum_reduce<<<16, 256>>>();

    static const int syrk_smem = 65536;
    cudaFuncSetAttribute(syrk_mma, cudaFuncAttributeMaxDynamicSharedMemorySize, syrk_smem);
    syrk_mma<<<dim3(3, NBY), 256, syrk_smem>>>();

    reduceG2_kernel<<<dim3(3, 64), 256>>>();

    static const int chol_smem = (C * (C + 1) / 2) * (int)sizeof(float);  // 131584
    cudaFuncSetAttribute(chol_kernel, cudaFuncAttributeMaxDynamicSharedMemorySize, chol_smem);
    chol_kernel<<<1, 256, chol_smem>>>(rows);

    static const int wh_smem = 81920;
    cudaFuncSetAttribute(whiten_fused, cudaFuncAttributeMaxDynamicSharedMemorySize, wh_smem);
    whiten_fused<<<rows / 128, 512, wh_smem>>>(x, out);
}

// round 8
// speedup vs baseline: 2.6609x; 1.0947x over previous
#include <cuda_runtime.h>
#include <cuda_bf16.h>
#include <math.h>
#include <stdint.h>

#define C 256
#define ROWS 131072
#define EPS 0.001f
#define NBY 128              // syrk split-K blocks
#define SY_NCH 32            // chunks per syrk block (1024/32)
#define WH_NCH 8             // whiten k-chunks (256/32)

// ---------------- scratch ----------------
__device__ float g_psum[NBY * C];
__device__ float g_pG2[(size_t)3 * NBY * 128 * 128];
__device__ float g_G[C * C];
__device__ float g_W[C * C];
__device__ float g_bias[C];
__device__ __nv_bfloat16 g_Whi[C * C];
__device__ __nv_bfloat16 g_Wlo[C * C];

__constant__ int c2_pi[3] = {0, 0, 1};
__constant__ int c2_pj[3] = {0, 1, 1};

// ---------------- helpers ----------------
__device__ __forceinline__ uint32_t smem_u32(const void* p) {
    uint32_t a;
    asm("{ .reg .u64 t; cvta.to.shared.u64 t, %1; cvt.u32.u64 %0, t; }" : "=r"(a) : "l"(p));
    return a;
}
__device__ __forceinline__ void cp16(uint32_t dst, const void* src) {
    asm volatile("cp.async.cg.shared.global [%0], [%1], 16;" :: "r"(dst), "l"(src));
}
#define CP_COMMIT() asm volatile("cp.async.commit_group;" ::: "memory")
#define CP_WAIT1()  asm volatile("cp.async.wait_group 1;" ::: "memory")
#define CP_WAIT0()  asm volatile("cp.async.wait_group 0;" ::: "memory")

__device__ __forceinline__ void mma_bf16(float* d, const uint32_t* a, const uint32_t* b) {
    asm volatile(
        "mma.sync.aligned.m16n8k16.row.col.f32.bf16.bf16.f32 "
        "{%0,%1,%2,%3}, {%4,%5,%6,%7}, {%8,%9}, {%0,%1,%2,%3};\n"
        : "+f"(d[0]), "+f"(d[1]), "+f"(d[2]), "+f"(d[3])
        : "r"(a[0]), "r"(a[1]), "r"(a[2]), "r"(a[3]), "r"(b[0]), "r"(b[1]));
}
__device__ __forceinline__ void ldsm4(uint32_t& d0, uint32_t& d1, uint32_t& d2, uint32_t& d3,
                                      uint32_t a) {
    asm volatile("ldmatrix.sync.aligned.m8n8.x4.shared.b16 {%0,%1,%2,%3}, [%4];"
                 : "=r"(d0), "=r"(d1), "=r"(d2), "=r"(d3) : "r"(a));
}
__device__ __forceinline__ uint32_t pack2(__nv_bfloat16 lo, __nv_bfloat16 hi) {
    return (uint32_t)__bfloat16_as_ushort(lo) | ((uint32_t)__bfloat16_as_ushort(hi) << 16);
}
// bank-conflict-free 16B piece placement within 8KB plane of [row][2 pieces]
__device__ __forceinline__ uint32_t sw16(int row, int pp) {
    return ((uint32_t)(((row << 1) | pp) ^ ((row >> 2) & 1))) << 4;
}
__device__ __forceinline__ void split8(const float* f, uint4& H, uint4& L) {
    __nv_bfloat16 h[8], l[8];
#pragma unroll
    for (int e = 0; e < 8; ++e) {
        h[e] = __float2bfloat16_rn(f[e]);
        l[e] = __float2bfloat16_rn(f[e] - __bfloat162float(h[e]));
    }
    H = make_uint4(pack2(h[0], h[1]), pack2(h[2], h[3]), pack2(h[4], h[5]), pack2(h[6], h[7]));
    L = make_uint4(pack2(l[0], l[1]), pack2(l[2], l[3]), pack2(l[4], l[5]), pack2(l[6], l[7]));
}

// ---------------- 1) SYRK fused: x fp32 -> smem transpose -> hi/lo planes -> mma ----------------
// smem bytes: fp32 stages [2][32 rows][256|128 ch] @0/32768; planes @65536: AH,AL,BH,BL 8KB each.
__global__ __launch_bounds__(256, 2) void syrk_fused(const float* __restrict__ x) {
    extern __shared__ char smem[];
    uint32_t sb = smem_u32(smem);
    uint32_t pl = sb + 65536;
    const float* sf = (const float*)smem;

    int tid = threadIdx.x, lane = tid & 31, warp = tid >> 5;
    int wm = warp >> 2, wn = warp & 3;          // 2x4 warps, warp tile 64x32
    int g4 = lane >> 2, t4 = lane & 3;
    int lrow = lane & 15, lpp = lane >> 4;
    int p = blockIdx.x;
    int ti = c2_pi[p];
    bool full = (p == 1);                       // reads all 256 channels
    size_t k0base = (size_t)blockIdx.y * (ROWS / NBY);
    uint32_t bBase = pl + (full ? 16384u : 0u);

    float acc[4][4][4];
#pragma unroll
    for (int a = 0; a < 4; ++a)
#pragma unroll
        for (int b = 0; b < 4; ++b)
#pragma unroll
            for (int r = 0; r < 4; ++r) acc[a][b][r] = 0.f;
    float csum = 0.f;

    auto issue = [&](int cc, int s) {
        size_t k0 = k0base + (size_t)cc * 32;
        if (full) {
#pragma unroll
            for (int q = 0; q < 8; ++q) {
                int idx = tid + 256 * q;        // 0..2047
                int row = idx >> 6, pc = idx & 63;
                cp16(sb + (uint32_t)s * 32768 + (uint32_t)row * 1024 + (uint32_t)pc * 16,
                     x + (k0 + row) * C + pc * 4);
            }
        } else {
#pragma unroll
            for (int q = 0; q < 4; ++q) {
                int idx = tid + 256 * q;        // 0..1023
                int row = idx >> 5, pc = idx & 31;
                cp16(sb + (uint32_t)s * 32768 + (uint32_t)row * 512 + (uint32_t)pc * 16,
                     x + (k0 + row) * C + ti * 128 + pc * 4);
            }
        }
    };

    issue(0, 0); CP_COMMIT();
    for (int c = 0; c < SY_NCH; ++c) {
        int s = c & 1;
        if (c + 1 < SY_NCH) { issue(c + 1, s ^ 1); CP_COMMIT(); CP_WAIT1(); }
        else CP_WAIT0();
        __syncthreads();   // ALL threads' stage-s cp.asyncs landed; prior MMA done with planes

        // convert stage s -> channel-major hi/lo planes; accumulate channel sums (p==1)
        if (full) {
            int ch = tid;
            uint32_t stg = (uint32_t)s * 8192;   // fp32 idx
            uint32_t boff = 65536u + (uint32_t)(ch >> 7) * 16384;
            int chl = ch & 127;
#pragma unroll
            for (int kp = 0; kp < 4; ++kp) {
                float f[8];
#pragma unroll
                for (int e = 0; e < 8; ++e) {
                    f[e] = sf[stg + (uint32_t)(kp * 8 + e) * 256 + ch];
                    csum += f[e];
                }
                uint4 H, L;
                split8(f, H, L);
                uint32_t off = (uint32_t)(kp >> 1) * 4096 + sw16(chl, kp & 1);
                *(uint4*)(smem + boff + off) = H;
                *(uint4*)(smem + boff + 8192 + off) = L;
            }
        } else {
            int ch = tid & 127, kb = tid >> 7;
            uint32_t stg = (uint32_t)s * 8192;
#pragma unroll
            for (int q = 0; q < 2; ++q) {
                int kp = kb * 2 + q;
                float f[8];
#pragma unroll
                for (int e = 0; e < 8; ++e)
                    f[e] = sf[stg + (uint32_t)(kp * 8 + e) * 128 + ch];
                uint4 H, L;
                split8(f, H, L);
                uint32_t off = (uint32_t)(kp >> 1) * 4096 + sw16(ch, kp & 1);
                *(uint4*)(smem + 65536 + off) = H;
                *(uint4*)(smem + 65536 + 8192 + off) = L;
            }
        }
        __syncthreads();   // planes ready

#pragma unroll
        for (int ks = 0; ks < 2; ++ks) {
            uint32_t AH = pl + (uint32_t)ks * 4096;
            uint32_t AL = AH + 8192;
            uint32_t BH = bBase + (uint32_t)ks * 4096;
            uint32_t BL = BH + 8192;
            uint32_t bh[4][2], bl[4][2];
#pragma unroll
            for (int np = 0; np < 2; ++np) {
                int nr = wn * 32 + np * 16 + lrow;
                ldsm4(bh[np * 2][0], bh[np * 2 + 1][0], bh[np * 2][1], bh[np * 2 + 1][1],
                      BH + sw16(nr, lpp));
                ldsm4(bl[np * 2][0], bl[np * 2 + 1][0], bl[np * 2][1], bl[np * 2 + 1][1],
                      BL + sw16(nr, lpp));
            }
#pragma unroll
            for (int mf = 0; mf < 4; ++mf) {
                int mr = wm * 64 + mf * 16 + lrow;
                uint32_t ah[4], al[4];
                ldsm4(ah[0], ah[1], ah[2], ah[3], AH + sw16(mr, lpp));
                ldsm4(al[0], al[1], al[2], al[3], AL + sw16(mr, lpp));
#pragma unroll
                for (int nf = 0; nf < 4; ++nf) {
                    mma_bf16(acc[mf][nf], ah, bh[nf]);
                    mma_bf16(acc[mf][nf], ah, bl[nf]);
                    mma_bf16(acc[mf][nf], al, bh[nf]);
                }
            }
        }
    }

    if (full) g_psum[blockIdx.y * C + tid] = csum;

    float* dst = g_pG2 + ((size_t)p * NBY + blockIdx.y) * 16384;
#pragma unroll
    for (int mf = 0; mf < 4; ++mf)
#pragma unroll
        for (int nf = 0; nf < 4; ++nf) {
            int r = wm * 64 + mf * 16 + g4;
            int cc = wn * 32 + nf * 8 + t4 * 2;
            dst[r * 128 + cc]           = acc[mf][nf][0];
            dst[r * 128 + cc + 1]       = acc[mf][nf][1];
            dst[(r + 8) * 128 + cc]     = acc[mf][nf][2];
            dst[(r + 8) * 128 + cc + 1] = acc[mf][nf][3];
        }
}

// ---------------- 2) deterministic reduction ----------------
__global__ __launch_bounds__(256) void reduceG2_kernel() {
    int p = blockIdx.x;
    int e = blockIdx.y * 256 + threadIdx.x;   // 0..16383
    const float* src = g_pG2 + (size_t)p * NBY * 16384 + e;
    float s = 0.f;
#pragma unroll 8
    for (int c = 0; c < NBY; ++c) s += src[(size_t)c * 16384];
    int a = e >> 7, b = e & 127;
    int gi = c2_pi[p] * 128 + a, gj = c2_pj[p] * 128 + b;
    g_G[gi * C + gj] = s;
    g_G[gj * C + gi] = s;
}

// ---------------- 3) mean + blocked Cholesky + blocked L^{-1} + bias + W split ----------------
extern "C" __global__ __launch_bounds__(256) void chol_kernel(int rows) {
    extern __shared__ float Lp[];     // packed lower tri, 32896 floats
    __shared__ float m[C];
    __shared__ float scrD[32 * 33];
    __shared__ float sdinv[32];
    __shared__ float scr[32 * 32];
    int tid = threadIdx.x, lane = tid & 31, warp = tid >> 5;

    {
        float s = 0.f;
#pragma unroll 8
        for (int b = 0; b < NBY; ++b) s += g_psum[b * C + tid];
        m[tid] = s / (float)rows;
    }
    __syncthreads();

    const int TOT = C * (C + 1) / 2;
    float scale = (1.f - EPS) / (float)(rows - 1);
    for (int idx = tid; idx < TOT; idx += 256) {
        int i = (int)((sqrtf(8.f * (float)idx + 1.f) - 1.f) * 0.5f);
        while ((i + 1) * (i + 2) / 2 <= idx) ++i;
        while (i * (i + 1) / 2 > idx) --i;
        int j = idx - i * (i + 1) / 2;
        float v = (g_G[i * C + j] - (float)rows * m[i] * m[j]) * scale;
        if (i == j) v += EPS;
        Lp[idx] = v;
    }
    __syncthreads();

    // ---- blocked Cholesky, panel width 32 ----
    for (int pb = 0; pb < 8; ++pb) {
        int base = pb * 32;
        for (int idx = tid; idx < 1024; idx += 256) {
            int i = idx >> 5, j = idx & 31;
            int gi = base + i;
            scrD[i * 33 + j] = (j <= i) ? Lp[gi * (gi + 1) / 2 + base + j] : 0.f;
        }
        __syncthreads();
        if (warp == 0) {
            for (int k = 0; k < 32; ++k) {
                if (lane == 0) scrD[k * 33 + k] = sqrtf(scrD[k * 33 + k]);
                __syncwarp();
                float inv = 1.f / scrD[k * 33 + k];
                if (lane > k) scrD[lane * 33 + k] *= inv;
                __syncwarp();
                if (lane > k) {
                    float lik = scrD[lane * 33 + k];
                    for (int j = k + 1; j <= lane; ++j)
                        scrD[lane * 33 + j] -= lik * scrD[j * 33 + k];
                }
                __syncwarp();
            }
        }
        __syncthreads();
        if (tid < 32) sdinv[tid] = 1.f / scrD[tid * 33 + tid];
        for (int idx = tid; idx < 1024; idx += 256) {
            int i = idx >> 5, j = idx & 31;
            if (j <= i) {
                int gi = base + i;
                Lp[gi * (gi + 1) / 2 + base + j] = scrD[i * 33 + j];
            }
        }
        __syncthreads();
        int R = 256 - base - 32;
        if (tid < R) {
            int gi = base + 32 + tid;
            int ro = gi * (gi + 1) / 2 + base;
            float r[32];
#pragma unroll
            for (int t = 0; t < 32; ++t) r[t] = Lp[ro + t];
#pragma unroll
            for (int k = 0; k < 32; ++k) {
                float s = r[k];
                for (int t = 0; t < k; ++t) s -= r[t] * scrD[k * 33 + t];
                r[k] = s * sdinv[k];
            }
#pragma unroll
            for (int t = 0; t < 32; ++t) Lp[ro + t] = r[t];
        }
        __syncthreads();
        if (R > 0) {
            int ti2 = tid >> 3, tj2 = tid & 7;
            for (int rt = 0; rt * 32 < R; ++rt) {
                int gi = base + 32 + rt * 32 + ti2;
                if (gi < 256) {
                    int roI = gi * (gi + 1) / 2;
                    float pi[32];
#pragma unroll
                    for (int t = 0; t < 32; ++t) pi[t] = Lp[roI + base + t];
                    for (int j0 = base + 32 + tj2 * 4; j0 <= gi; j0 += 32) {
                        int j1 = min(j0 + 1, 255), j2 = min(j0 + 2, 255), j3 = min(j0 + 3, 255);
                        int ro0 = j0 * (j0 + 1) / 2 + base;
                        int ro1 = j1 * (j1 + 1) / 2 + base;
                        int ro2 = j2 * (j2 + 1) / 2 + base;
                        int ro3 = j3 * (j3 + 1) / 2 + base;
                        float a0 = 0, a1 = 0, a2 = 0, a3 = 0;
#pragma unroll
                        for (int t = 0; t < 32; ++t) {
                            float pv = pi[t];
                            a0 += pv * Lp[ro0 + t];
                            a1 += pv * Lp[ro1 + t];
                            a2 += pv * Lp[ro2 + t];
                            a3 += pv * Lp[ro3 + t];
                        }
                        Lp[roI + j0] -= a0;
                        if (j0 + 1 <= gi) Lp[roI + j0 + 1] -= a1;
                        if (j0 + 2 <= gi) Lp[roI + j0 + 2] -= a2;
                        if (j0 + 3 <= gi) Lp[roI + j0 + 3] -= a3;
                    }
                }
            }
        }
        __syncthreads();
    }

    // ---- blocked inversion: diagonal 32x32 blocks in registers ----
    {
        int b = tid >> 5, j = tid & 31;
        int rb = b * 32;
        float w[32];
#pragma unroll
        for (int i = 0; i < 32; ++i) {
            float s = (i == j) ? 1.f : 0.f;
            const float* lrow = &Lp[(rb + i) * (rb + i + 1) / 2 + rb];
#pragma unroll
            for (int k = 0; k < 32; ++k)
                if (k < i) s -= lrow[k] * w[k];
            w[i] = (i >= j) ? s / lrow[i] : 0.f;
        }
#pragma unroll
        for (int i = 0; i < 32; ++i) g_W[(rb + i) * C + rb + j] = w[i];
    }
    __syncthreads();
    for (int idx = tid; idx < C * C; idx += 256) {
        int r = idx >> 8, cc = idx & 255;
        if (cc > r) g_W[idx] = 0.f;
    }
    __syncthreads();

    // off-diagonal blocks
    {
        int r = tid >> 3, c4 = (tid & 7) * 4;
        for (int step = 1; step < 8; ++step) {
            for (int bj = 0; bj + step < 8; ++bj) {
                int bi = bj + step;
                float a0 = 0, a1 = 0, a2 = 0, a3 = 0;
                const float* lrow = &Lp[(bi * 32 + r) * (bi * 32 + r + 1) / 2];
                for (int kb = bj; kb < bi; ++kb) {
#pragma unroll 8
                    for (int kk = 0; kk < 32; ++kk) {
                        float lv = lrow[kb * 32 + kk];
                        const float* wr = &g_W[(kb * 32 + kk) * C + bj * 32 + c4];
                        a0 += lv * wr[0]; a1 += lv * wr[1]; a2 += lv * wr[2]; a3 += lv * wr[3];
                    }
                }
                scr[r * 32 + c4 + 0] = a0; scr[r * 32 + c4 + 1] = a1;
                scr[r * 32 + c4 + 2] = a2; scr[r * 32 + c4 + 3] = a3;
                __syncthreads();
                float o0 = 0, o1 = 0, o2 = 0, o3 = 0;
#pragma unroll 8
                for (int kk = 0; kk < 32; ++kk) {
                    float dv = g_W[(bi * 32 + r) * C + bi * 32 + kk];
                    o0 += dv * scr[kk * 32 + c4 + 0];
                    o1 += dv * scr[kk * 32 + c4 + 1];
                    o2 += dv * scr[kk * 32 + c4 + 2];
                    o3 += dv * scr[kk * 32 + c4 + 3];
                }
                g_W[(bi * 32 + r) * C + bj * 32 + c4 + 0] = -o0;
                g_W[(bi * 32 + r) * C + bj * 32 + c4 + 1] = -o1;
                g_W[(bi * 32 + r) * C + bj * 32 + c4 + 2] = -o2;
                g_W[(bi * 32 + r) * C + bj * 32 + c4 + 3] = -o3;
                __syncthreads();
            }
        }
    }

    {
        float s = 0.f;
#pragma unroll 4
        for (int j = 0; j <= tid; ++j) s += g_W[tid * C + j] * m[j];
        g_bias[tid] = s;
    }

    for (int idx = tid; idx < C * C; idx += 256) {
        float w = g_W[idx];
        __nv_bfloat16 h = __float2bfloat16_rn(w);
        g_Whi[idx] = h;
        g_Wlo[idx] = __float2bfloat16_rn(w - __bfloat162float(h));
    }
}

// ---------------- 4) whitening fused: x fp32 regs -> hi/lo planes -> mma ----------------
// smem: XH 8KB @0, XL 8KB @8192, W stages @16384: [s2][pl2][sl2][8KB] (64KB)
__global__ __launch_bounds__(512, 1) void whiten_fused(const float* __restrict__ x,
                                                       float* __restrict__ out) {
    extern __shared__ char smem[];
    __shared__ float sbias[C];
    uint32_t sb = smem_u32(smem);

    int tid = threadIdx.x, lane = tid & 31, warp = tid >> 5;
    int wm = warp >> 2, wn = warp & 3;      // 4x4 warps, warp tile 32x64
    int g4 = lane >> 2, t4 = lane & 3;
    int lrow = lane & 15, lpp = lane >> 4;
    size_t m0 = (size_t)blockIdx.x * 128;

    if (tid < C) sbias[tid] = g_bias[tid];

    float acc[2][8][4];
#pragma unroll
    for (int a = 0; a < 2; ++a)
#pragma unroll
        for (int b = 0; b < 8; ++b)
#pragma unroll
            for (int r = 0; r < 4; ++r) acc[a][b][r] = 0.f;

    int xrow = tid >> 2, xpp = tid & 3;
    const float* xp = x + (m0 + xrow) * C + xpp * 8;

    auto issueW = [&](int cc, int s) {
        int k0 = cc * 32;
#pragma unroll
        for (int q = 0; q < 4; ++q) {
            int idx = tid + 512 * q;
            int plm = idx >> 10, rem = idx & 1023;
            int n = rem >> 2, sl = (rem >> 1) & 1, pp = rem & 1;
            const __nv_bfloat16* plane = plm ? g_Wlo : g_Whi;
            cp16(sb + 16384u + (uint32_t)s * 32768 + (uint32_t)plm * 16384 +
                     (uint32_t)sl * 8192 + sw16(n, pp),
                 plane + (size_t)n * C + k0 + sl * 16 + pp * 8);
        }
    };

    float4 xv0 = *(const float4*)(xp);
    float4 xv1 = *(const float4*)(xp + 4);
    issueW(0, 0); CP_COMMIT();

    for (int c = 0; c < WH_NCH; ++c) {
        int s = c & 1;
        __syncthreads();   // prev MMA done reading X planes + W stage s^1
        // convert registers -> X planes
        {
            float f[8] = {xv0.x, xv0.y, xv0.z, xv0.w, xv1.x, xv1.y, xv1.z, xv1.w};
            uint4 H, L;
            split8(f, H, L);
            uint32_t off = (uint32_t)(xpp >> 1) * 4096 + sw16(xrow, xpp & 1);
            *(uint4*)(smem + off) = H;
            *(uint4*)(smem + 8192 + off) = L;
        }
        if (c + 1 < WH_NCH) {
            xv0 = *(const float4*)(xp + (c + 1) * 32);
            xv1 = *(const float4*)(xp + (c + 1) * 32 + 4);
            issueW(c + 1, s ^ 1); CP_COMMIT(); CP_WAIT1();
        } else CP_WAIT0();
        __syncthreads();

#pragma unroll
        for (int ks = 0; ks < 2; ++ks) {
            uint32_t XH = sb + (uint32_t)ks * 4096;
            uint32_t XL = XH + 8192;
            uint32_t WHb = sb + 16384u + (uint32_t)s * 32768 + (uint32_t)ks * 8192;
            uint32_t WLb = WHb + 16384;
            uint32_t bh[8][2], bl[8][2];
#pragma unroll
            for (int np = 0; np < 4; ++np) {
                int nr = wn * 64 + np * 16 + lrow;
                ldsm4(bh[np * 2][0], bh[np * 2 + 1][0], bh[np * 2][1], bh[np * 2 + 1][1],
                      WHb + sw16(nr, lpp));
                ldsm4(bl[np * 2][0], bl[np * 2 + 1][0], bl[np * 2][1], bl[np * 2 + 1][1],
                      WLb + sw16(nr, lpp));
            }
#pragma unroll
            for (int mf = 0; mf < 2; ++mf) {
                int mr = wm * 32 + mf * 16 + lrow;
                uint32_t ah[4], al[4];
                ldsm4(ah[0], ah[1], ah[2], ah[3], XH + sw16(mr, lpp));
                ldsm4(al[0], al[1], al[2], al[3], XL + sw16(mr, lpp));
#pragma unroll
                for (int nf = 0; nf < 8; ++nf) {
                    mma_bf16(acc[mf][nf], ah, bh[nf]);
                    mma_bf16(acc[mf][nf], ah, bl[nf]);
                    mma_bf16(acc[mf][nf], al, bh[nf]);
                }
            }
        }
    }

    // epilogue
#pragma unroll
    for (int mf = 0; mf < 2; ++mf)
#pragma unroll
        for (int nf = 0; nf < 8; ++nf) {
            int r = wm * 32 + mf * 16 + g4;
            int cc = wn * 64 + nf * 8 + t4 * 2;
            float b0 = sbias[cc], b1 = sbias[cc + 1];
            *(float2*)&out[(m0 + r) * C + cc]     = make_float2(acc[mf][nf][0] - b0, acc[mf][nf][1] - b1);
            *(float2*)&out[(m0 + r + 8) * C + cc] = make_float2(acc[mf][nf][2] - b0, acc[mf][nf][3] - b1);
        }
}

// ---------------- launch ----------------
extern "C" void kernel_launch(void* const* d_in, const int* in_sizes, int n_in,
                              void* d_out, int out_size) {
    const float* x = (const float*)d_in[0];
    float* out = (float*)d_out;
    int rows = in_sizes[0] / C;          // 131072

    static const int syrk_smem = 98304;
    cudaFuncSetAttribute(syrk_fused, cudaFuncAttributeMaxDynamicSharedMemorySize, syrk_smem);
    syrk_fused<<<dim3(3, NBY), 256, syrk_smem>>>(x);

    reduceG2_kernel<<<dim3(3, 64), 256>>>();

    static const int chol_smem = (C * (C + 1) / 2) * (int)sizeof(float);  // 131584
    cudaFuncSetAttribute(chol_kernel, cudaFuncAttributeMaxDynamicSharedMemorySize, chol_smem);
    chol_kernel<<<1, 256, chol_smem>>>(rows);

    static const int wh_smem = 81920;
    cudaFuncSetAttribute(whiten_fused, cudaFuncAttributeMaxDynamicSharedMemorySize, wh_smem);
    whiten_fused<<<rows / 128, 512, wh_smem>>>(x, out);
}